// round 6
// baseline (speedup 1.0000x reference)
#include <cuda_runtime.h>
#include <cuda_fp16.h>
#include <math.h>
#include <math_constants.h>
#include <stdint.h>

#define B_    2
#define L_    2048
#define D_    2048
#define H_    16
#define KVH_  4
#define HD_   128
#define EPS_  1e-6f

typedef __half h16;

// ---------------------------------------------------------------------------
// Static scratch
// ---------------------------------------------------------------------------
__device__ float g_q [B_*L_*D_];
__device__ float g_k [B_*L_*KVH_*HD_];
__device__ float g_v [B_*L_*KVH_*HD_];

__device__ h16 g_xh [B_*L_*D_],      g_xl [B_*L_*D_];
__device__ h16 g_wq [D_*D_];
__device__ h16 g_wk [KVH_*HD_*D_];
__device__ h16 g_wv [KVH_*HD_*D_];
__device__ h16 g_wo [D_*D_];
__device__ h16 g_qh [B_*L_*D_],      g_ql [B_*L_*D_];
__device__ h16 g_kh [B_*L_*KVH_*HD_];
__device__ h16 g_vt [B_*KVH_*HD_*L_];                 // V transposed [b][kvh][d][L]
__device__ h16 g_aoh[B_*L_*D_],      g_aol[B_*L_*D_];

// ---------------------------------------------------------------------------
// PTX helpers
// ---------------------------------------------------------------------------
__device__ __forceinline__ void mma_f16(float* c, const uint32_t* a, const uint32_t* b) {
    asm volatile(
        "mma.sync.aligned.m16n8k16.row.col.f32.f16.f16.f32 "
        "{%0,%1,%2,%3}, {%4,%5,%6,%7}, {%8,%9}, {%0,%1,%2,%3};\n"
        : "+f"(c[0]), "+f"(c[1]), "+f"(c[2]), "+f"(c[3])
        : "r"(a[0]), "r"(a[1]), "r"(a[2]), "r"(a[3]), "r"(b[0]), "r"(b[1]));
}

// fp16-accumulator MMA (2x rate on the HMMA pipe); C = {f16x2, f16x2}
__device__ __forceinline__ void mma_f16acc(uint32_t* c, const uint32_t* a, const uint32_t* b) {
    asm volatile(
        "mma.sync.aligned.m16n8k16.row.col.f16.f16.f16.f16 "
        "{%0,%1}, {%2,%3,%4,%5}, {%6,%7}, {%0,%1};\n"
        : "+r"(c[0]), "+r"(c[1])
        : "r"(a[0]), "r"(a[1]), "r"(a[2]), "r"(a[3]), "r"(b[0]), "r"(b[1]));
}

__device__ __forceinline__ void add_f16acc(float* cf, const uint32_t* cl) {
    float2 l0 = __half22float2(*reinterpret_cast<const half2*>(&cl[0]));
    float2 l1 = __half22float2(*reinterpret_cast<const half2*>(&cl[1]));
    cf[0] += l0.x; cf[1] += l0.y; cf[2] += l1.x; cf[3] += l1.y;
}

__device__ __forceinline__ void cp16(const h16* dst_s, const h16* src_g) {
    uint32_t d = (uint32_t)__cvta_generic_to_shared(dst_s);
    asm volatile("cp.async.cg.shared.global [%0], [%1], 16;\n"
                 :: "r"(d), "l"(src_g) : "memory");
}
__device__ __forceinline__ void cp_commit() {
    asm volatile("cp.async.commit_group;\n" ::: "memory");
}
template<int N>
__device__ __forceinline__ void cp_wait() {
    asm volatile("cp.async.wait_group %0;\n" :: "n"(N) : "memory");
}

__device__ __forceinline__ uint32_t pack2(h16 a, h16 b) {
    uint32_t x = *reinterpret_cast<unsigned short*>(&a);
    uint32_t y = *reinterpret_cast<unsigned short*>(&b);
    return x | (y << 16);
}

__device__ __forceinline__ void split1(float x, unsigned short& h, unsigned short& l) {
    h16 hh = __float2half_rn(x);
    h16 ll = __float2half_rn(x - __half2float(hh));
    h = *reinterpret_cast<unsigned short*>(&hh);
    l = *reinterpret_cast<unsigned short*>(&ll);
}

// ---------------------------------------------------------------------------
// Projection GEMM: C[M,N] fp32 = (Ah+Al)[M,K] * Bh[N,K]^T
// Main product fp32-acc MMA; correction product fp16-acc MMA chained over K.
// ---------------------------------------------------------------------------
#define BM 128
#define BN 128
#define BK 32
#define APAD 40

#define SM_A_HALVES (2*2*BM*APAD)
#define SM_B_HALVES (2*BN*APAD)
#define SMEM_TB_BYTES ((SM_A_HALVES + SM_B_HALVES)*2)   // 61440

__global__ __launch_bounds__(256, 1)
void k_gemm_bt(const h16* __restrict__ Ah, const h16* __restrict__ Al, int lda,
               const h16* __restrict__ Bh, int ldb,
               float* __restrict__ C, int ldc, int K)
{
    extern __shared__ h16 sh[];
    h16* sA = sh;
    h16* sB = sh + SM_A_HALVES;

    const int tid = threadIdx.x;
    const int m0 = blockIdx.y * BM;
    const int n0 = blockIdx.x * BN;

    const h16* Ap[2] = { Ah + (size_t)m0 * lda, Al + (size_t)m0 * lda };
    const h16* Bp    =   Bh + (size_t)n0 * ldb;

    const int lane = tid & 31;
    const int g    = lane >> 2;
    const int t    = lane & 3;
    const int warp = tid >> 5;
    const int wm   = warp >> 2;
    const int wn   = warp & 3;

    float acc[4][4][4];
    uint32_t accl[4][4][2];
#pragma unroll
    for (int i = 0; i < 4; i++)
#pragma unroll
        for (int j = 0; j < 4; j++) {
#pragma unroll
            for (int c = 0; c < 4; c++) acc[i][j][c] = 0.f;
            accl[i][j][0] = 0u; accl[i][j][1] = 0u;
        }

    auto load_stage = [&](int s, int k0) {
#pragma unroll
        for (int p = 0; p < 2; p++) {
#pragma unroll
            for (int i = 0; i < 2; i++) {
                int c   = tid + i * 256;
                int row = c >> 2, kc = c & 3;
                cp16(sA + (size_t)(s*2+p)*BM*APAD + row*APAD + kc*8,
                     Ap[p] + (size_t)row * lda + k0 + kc*8);
            }
        }
#pragma unroll
        for (int i = 0; i < 2; i++) {
            int c   = tid + i * 256;
            int row = c >> 2, kc = c & 3;
            cp16(sB + (size_t)s*BN*APAD + row*APAD + kc*8,
                 Bp + (size_t)row * ldb + k0 + kc*8);
        }
    };

    const int nk = K / BK;
    load_stage(0, 0);
    cp_commit();

    for (int ks = 0; ks < nk; ks++) {
        const int buf = ks & 1;
        if (ks + 1 < nk) {
            load_stage(buf ^ 1, (ks + 1) * BK);
            cp_commit();
            cp_wait<1>();
        } else {
            cp_wait<0>();
        }
        __syncthreads();

        const h16* sAh = sA + (size_t)(buf*2+0)*BM*APAD;
        const h16* sAl = sA + (size_t)(buf*2+1)*BM*APAD;
        const h16* sBh = sB + (size_t)buf*BN*APAD;

#pragma unroll
        for (int kk = 0; kk < 2; kk++) {
            const int ko = kk * 16;

            uint32_t ah[4][4], alr[4][4];
#pragma unroll
            for (int mt = 0; mt < 4; mt++) {
                const int r = wm*64 + mt*16 + g;
                const h16* p0 = sAh + r*APAD + ko + 2*t;
                ah[mt][0] = *(const uint32_t*)(p0);
                ah[mt][1] = *(const uint32_t*)(p0 + 8*APAD);
                ah[mt][2] = *(const uint32_t*)(p0 + 8);
                ah[mt][3] = *(const uint32_t*)(p0 + 8*APAD + 8);
                const h16* p1 = sAl + r*APAD + ko + 2*t;
                alr[mt][0] = *(const uint32_t*)(p1);
                alr[mt][1] = *(const uint32_t*)(p1 + 8*APAD);
                alr[mt][2] = *(const uint32_t*)(p1 + 8);
                alr[mt][3] = *(const uint32_t*)(p1 + 8*APAD + 8);
            }

            uint32_t bh[4][2];
#pragma unroll
            for (int nt = 0; nt < 4; nt++) {
                const int n = wn*32 + nt*8 + g;
                const h16* p0 = sBh + n*APAD + ko + 2*t;
                bh[nt][0] = *(const uint32_t*)(p0);
                bh[nt][1] = *(const uint32_t*)(p0 + 8);
            }

#pragma unroll
            for (int mt = 0; mt < 4; mt++)
#pragma unroll
                for (int nt = 0; nt < 4; nt++) {
                    mma_f16(acc[mt][nt], ah[mt], bh[nt]);
                    mma_f16acc(accl[mt][nt], alr[mt], bh[nt]);
                }
        }
        __syncthreads();
    }

#pragma unroll
    for (int mt = 0; mt < 4; mt++) {
        const int r = m0 + wm*64 + mt*16 + g;
#pragma unroll
        for (int nt = 0; nt < 4; nt++) {
            add_f16acc(acc[mt][nt], accl[mt][nt]);
            const int c = n0 + wn*32 + nt*8 + 2*t;
            *reinterpret_cast<float2*>(&C[(size_t)r     * ldc + c]) =
                make_float2(acc[mt][nt][0], acc[mt][nt][1]);
            *reinterpret_cast<float2*>(&C[(size_t)(r+8) * ldc + c]) =
                make_float2(acc[mt][nt][2], acc[mt][nt][3]);
        }
    }
}

// ---------------------------------------------------------------------------
// fp32 -> (hi, lo) fp16 split  /  fp32 -> fp16 convert
// ---------------------------------------------------------------------------
__global__ void k_split(const float4* __restrict__ X,
                        ushort4* __restrict__ Hi, ushort4* __restrict__ Lo, int n4)
{
    int i = blockIdx.x * blockDim.x + threadIdx.x;
    if (i >= n4) return;
    float4 v = X[i];
    ushort4 hv, lv;
    split1(v.x, hv.x, lv.x);
    split1(v.y, hv.y, lv.y);
    split1(v.z, hv.z, lv.z);
    split1(v.w, hv.w, lv.w);
    Hi[i] = hv;
    Lo[i] = lv;
}

__global__ void k_cvt(const float4* __restrict__ X, ushort4* __restrict__ Hi, int n4)
{
    int i = blockIdx.x * blockDim.x + threadIdx.x;
    if (i >= n4) return;
    float4 v = X[i];
    h16 a = __float2half_rn(v.x), b = __float2half_rn(v.y);
    h16 c = __float2half_rn(v.z), d = __float2half_rn(v.w);
    ushort4 hv;
    hv.x = *reinterpret_cast<unsigned short*>(&a);
    hv.y = *reinterpret_cast<unsigned short*>(&b);
    hv.z = *reinterpret_cast<unsigned short*>(&c);
    hv.w = *reinterpret_cast<unsigned short*>(&d);
    Hi[i] = hv;
}

// ---------------------------------------------------------------------------
// RMSNorm + RoPE, fp32 in -> fp16 hi (+ optional lo) planes. One warp/(b,l,h).
// ---------------------------------------------------------------------------
__global__ void rms_rope_split_kernel(const float* __restrict__ X,
                                      const float* __restrict__ gamma,
                                      h16* __restrict__ Xh, h16* __restrict__ Xl,
                                      int heads) {
    const int warp = (blockIdx.x * blockDim.x + threadIdx.x) >> 5;
    const int lane = threadIdx.x & 31;
    const int h = warp % heads;
    const int l = (warp / heads) % L_;
    const int b = warp / (heads * L_);

    const size_t base = ((size_t)(b * L_ + l) * heads + h) * HD_;
    const float* vec = X + base;

    const int p0 = lane, p1 = lane + 32;
    float x0a = vec[2*p0],   x1a = vec[2*p0+1];
    float x0b = vec[2*p1],   x1b = vec[2*p1+1];

    float ss = x0a*x0a + x1a*x1a + x0b*x0b + x1b*x1b;
#pragma unroll
    for (int off = 16; off; off >>= 1)
        ss += __shfl_xor_sync(0xffffffffu, ss, off);

    const float inv = rsqrtf(ss * (1.0f / HD_) + EPS_);
    const float LOG2_THETA = 13.287712379549449f;
    const float fl = (float)l;

    unsigned short hh, ll;
    {
        float g0 = gamma[2*p0], g1 = gamma[2*p0+1];
        float re = x0a * inv * g0, im = x1a * inv * g1;
        float fr = fl * exp2f(-(2.0f * p0 / (float)HD_) * LOG2_THETA);
        float s, c; sincosf(fr, &s, &c);
        float o0 = re * c - im * s, o1 = re * s + im * c;
        split1(o0, hh, ll);
        ((unsigned short*)Xh)[base + 2*p0] = hh;
        if (Xl) ((unsigned short*)Xl)[base + 2*p0] = ll;
        split1(o1, hh, ll);
        ((unsigned short*)Xh)[base + 2*p0+1] = hh;
        if (Xl) ((unsigned short*)Xl)[base + 2*p0+1] = ll;
    }
    {
        float g0 = gamma[2*p1], g1 = gamma[2*p1+1];
        float re = x0b * inv * g0, im = x1b * inv * g1;
        float fr = fl * exp2f(-(2.0f * p1 / (float)HD_) * LOG2_THETA);
        float s, c; sincosf(fr, &s, &c);
        float o0 = re * c - im * s, o1 = re * s + im * c;
        split1(o0, hh, ll);
        ((unsigned short*)Xh)[base + 2*p1] = hh;
        if (Xl) ((unsigned short*)Xl)[base + 2*p1] = ll;
        split1(o1, hh, ll);
        ((unsigned short*)Xh)[base + 2*p1+1] = hh;
        if (Xl) ((unsigned short*)Xl)[base + 2*p1+1] = ll;
    }
}

// ---------------------------------------------------------------------------
// V transpose: v fp32 [b][l][kvh][d] -> vt fp16 [b][kvh][d][L]
// ---------------------------------------------------------------------------
__global__ void k_vtrans(const float* __restrict__ V, h16* __restrict__ Vt)
{
    __shared__ float tile[32][33];
    const int tx = threadIdx.x & 31;
    const int ty = threadIdx.x >> 5;
    const int l0 = blockIdx.x * 32;
    const int d0 = blockIdx.y * 32;
    const int z  = blockIdx.z;
    const int b  = z >> 2, kvh = z & 3;

#pragma unroll
    for (int i = 0; i < 4; i++) {
        int l = l0 + ty + i*8;
        tile[ty + i*8][tx] =
            V[((size_t)(b*L_ + l) * KVH_ + kvh) * HD_ + d0 + tx];
    }
    __syncthreads();
#pragma unroll
    for (int i = 0; i < 4; i++) {
        int d = d0 + ty + i*8;
        h16 val = __float2half_rn(tile[tx][ty + i*8]);
        size_t idx = ((size_t)(b*KVH_ + kvh) * HD_ + d) * L_ + l0 + tx;
        Vt[idx] = val;
    }
}

// ---------------------------------------------------------------------------
// Fused flash attention. Main MMAs fp32-acc; correction MMAs fp16-acc.
// ---------------------------------------------------------------------------
#define QPAD 136
#define VPAD 72

#define QPL  (128*QPAD)
#define KPL  (64*QPAD)
#define VPL  (128*VPAD)
#define QS_OFF 0
#define KS_OFF (2*QPL)
#define VS_OFF (KS_OFF + 2*KPL)
#define MS_OFF_H (VS_OFF + 2*VPL)
#define FA_SMEM_BYTES (MS_OFF_H*2 + 2*64*4)   // 141824

__global__ __launch_bounds__(256, 1)
void k_flash(const h16* __restrict__ qh, const h16* __restrict__ ql,
             const h16* __restrict__ kh,
             const h16* __restrict__ vt,
             const int* __restrict__ mask,
             h16* __restrict__ aoh, h16* __restrict__ aol)
{
    extern __shared__ h16 sm[];
    h16*   Qs = sm + QS_OFF;
    h16*   Ks = sm + KS_OFF;
    h16*   Vs = sm + VS_OFF;
    float* Ms = (float*)(sm + MS_OFF_H);

    const int tid  = threadIdx.x;
    const int lane = tid & 31;
    const int g    = lane >> 2;
    const int t    = lane & 3;
    const int w    = tid >> 5;

    const int qt = blockIdx.x, h = blockIdx.y, b = blockIdx.z;
    const int kvh = h >> 2;
    const int q0  = qt * 128;

    const h16* Qg[2] = { qh + ((size_t)(b*L_ + q0)) * D_ + h * HD_,
                         ql + ((size_t)(b*L_ + q0)) * D_ + h * HD_ };
    const h16* Kg = kh + ((size_t)(b*L_)) * (KVH_*HD_) + kvh * HD_;
    const h16* Vg = vt + ((size_t)(b*KVH_ + kvh)) * HD_ * L_;

#pragma unroll
    for (int p = 0; p < 2; p++)
#pragma unroll
        for (int i = 0; i < 8; i++) {
            int c = tid + i * 256;
            int row = c >> 4, ch = c & 15;
            cp16(Qs + p*QPL + row*QPAD + ch*8, Qg[p] + (size_t)row * D_ + ch*8);
        }

    auto load_stage = [&](int s, int kt) {
        const int j0 = kt * 64;
#pragma unroll
        for (int i = 0; i < 4; i++) {
            int c = tid + i * 256;
            int row = c >> 4, ch = c & 15;
            cp16(Ks + s*KPL + row*QPAD + ch*8,
                 Kg + (size_t)(j0 + row) * (KVH_*HD_) + ch*8);
        }
#pragma unroll
        for (int i = 0; i < 4; i++) {
            int c = tid + i * 256;
            int row = c >> 3, ch = c & 7;
            cp16(Vs + s*VPL + row*VPAD + ch*8,
                 Vg + (size_t)row * L_ + j0 + ch*8);
        }
        if (tid < 64)
            Ms[s*64 + tid] = mask[b*L_ + j0 + tid] ? 0.f : -1e30f;
    };

    load_stage(0, 0);
    cp_commit();

    float o[16][4];
#pragma unroll
    for (int i = 0; i < 16; i++)
#pragma unroll
        for (int c = 0; c < 4; c++) o[i][c] = 0.f;

    float mprev0 = -1e30f, mprev1 = -1e30f;
    float lsum0 = 0.f, lsum1 = 0.f;
    const float sc = 0.08838834764831845f;

    const int NT_ = L_ / 64;
    for (int kt = 0; kt < NT_; kt++) {
        const int buf = kt & 1;
        if (kt + 1 < NT_) {
            load_stage(buf ^ 1, kt + 1);
            cp_commit();
            cp_wait<1>();
        } else {
            cp_wait<0>();
        }
        __syncthreads();

        // ---- S = Q K^T : hi on fp32-acc, lo on fp16-acc chained over k ----
        float s[8][4];
        uint32_t sl[8][2];
#pragma unroll
        for (int nt = 0; nt < 8; nt++) {
#pragma unroll
            for (int c = 0; c < 4; c++) s[nt][c] = 0.f;
            sl[nt][0] = 0u; sl[nt][1] = 0u;
        }

        const h16* qbh = Qs + (w*16 + g)*QPAD + 2*t;
        const h16* qbl = qbh + QPL;
        const h16* kb  = Ks + buf*KPL + g*QPAD + 2*t;

#pragma unroll
        for (int kk = 0; kk < 8; kk++) {
            const int ko = kk * 16;
            uint32_t ah[4], al[4];
            ah[0] = *(const uint32_t*)(qbh + ko);
            ah[1] = *(const uint32_t*)(qbh + ko + 8*QPAD);
            ah[2] = *(const uint32_t*)(qbh + ko + 8);
            ah[3] = *(const uint32_t*)(qbh + ko + 8*QPAD + 8);
            al[0] = *(const uint32_t*)(qbl + ko);
            al[1] = *(const uint32_t*)(qbl + ko + 8*QPAD);
            al[2] = *(const uint32_t*)(qbl + ko + 8);
            al[3] = *(const uint32_t*)(qbl + ko + 8*QPAD + 8);
#pragma unroll
            for (int nt = 0; nt < 8; nt++) {
                uint32_t bh[2];
                const h16* pk = kb + nt*8*QPAD + ko;
                bh[0] = *(const uint32_t*)(pk);
                bh[1] = *(const uint32_t*)(pk + 8);
                mma_f16(s[nt], ah, bh);
                mma_f16acc(sl[nt], al, bh);
            }
        }
#pragma unroll
        for (int nt = 0; nt < 8; nt++) add_f16acc(s[nt], sl[nt]);

        // ---- online softmax on fragments ----
        const float* msf = Ms + buf*64;
        float m0 = -1e30f, m1 = -1e30f;
#pragma unroll
        for (int nt = 0; nt < 8; nt++) {
            float b0 = msf[8*nt + 2*t], b1 = msf[8*nt + 2*t + 1];
            s[nt][0] = s[nt][0]*sc + b0;
            s[nt][1] = s[nt][1]*sc + b1;
            s[nt][2] = s[nt][2]*sc + b0;
            s[nt][3] = s[nt][3]*sc + b1;
            m0 = fmaxf(m0, fmaxf(s[nt][0], s[nt][1]));
            m1 = fmaxf(m1, fmaxf(s[nt][2], s[nt][3]));
        }
        m0 = fmaxf(m0, __shfl_xor_sync(0xffffffffu, m0, 1));
        m0 = fmaxf(m0, __shfl_xor_sync(0xffffffffu, m0, 2));
        m1 = fmaxf(m1, __shfl_xor_sync(0xffffffffu, m1, 1));
        m1 = fmaxf(m1, __shfl_xor_sync(0xffffffffu, m1, 2));

        const float mn0 = fmaxf(mprev0, m0);
        const float mn1 = fmaxf(mprev1, m1);
        const float alpha0 = __expf(mprev0 - mn0);
        const float alpha1 = __expf(mprev1 - mn1);
        mprev0 = mn0; mprev1 = mn1;

        float sum0 = 0.f, sum1 = 0.f;
#pragma unroll
        for (int nt = 0; nt < 8; nt++) {
            s[nt][0] = __expf(s[nt][0] - mn0);
            s[nt][1] = __expf(s[nt][1] - mn0);
            s[nt][2] = __expf(s[nt][2] - mn1);
            s[nt][3] = __expf(s[nt][3] - mn1);
            sum0 += s[nt][0] + s[nt][1];
            sum1 += s[nt][2] + s[nt][3];
        }
        sum0 += __shfl_xor_sync(0xffffffffu, sum0, 1);
        sum0 += __shfl_xor_sync(0xffffffffu, sum0, 2);
        sum1 += __shfl_xor_sync(0xffffffffu, sum1, 1);
        sum1 += __shfl_xor_sync(0xffffffffu, sum1, 2);
        lsum0 = lsum0 * alpha0 + sum0;
        lsum1 = lsum1 * alpha1 + sum1;

#pragma unroll
        for (int nt = 0; nt < 16; nt++) {
            o[nt][0] *= alpha0; o[nt][1] *= alpha0;
            o[nt][2] *= alpha1; o[nt][3] *= alpha1;
        }

        // ---- P fragments (register-local split to fp16 hi/lo) ----
        uint32_t pah[4][4], pal[4][4];
#pragma unroll
        for (int kk = 0; kk < 4; kk++) {
            const int n0t = 2*kk, n1t = 2*kk + 1;
            float p00 = s[n0t][0], p01 = s[n0t][1], p02 = s[n0t][2], p03 = s[n0t][3];
            float p10 = s[n1t][0], p11 = s[n1t][1], p12 = s[n1t][2], p13 = s[n1t][3];
            h16 h00 = __float2half_rn(p00), h01 = __float2half_rn(p01);
            h16 h02 = __float2half_rn(p02), h03 = __float2half_rn(p03);
            h16 h10 = __float2half_rn(p10), h11 = __float2half_rn(p11);
            h16 h12 = __float2half_rn(p12), h13 = __float2half_rn(p13);
            pah[kk][0] = pack2(h00, h01);
            pah[kk][1] = pack2(h02, h03);
            pah[kk][2] = pack2(h10, h11);
            pah[kk][3] = pack2(h12, h13);
            pal[kk][0] = pack2(__float2half_rn(p00 - __half2float(h00)),
                               __float2half_rn(p01 - __half2float(h01)));
            pal[kk][1] = pack2(__float2half_rn(p02 - __half2float(h02)),
                               __float2half_rn(p03 - __half2float(h03)));
            pal[kk][2] = pack2(__float2half_rn(p10 - __half2float(h10)),
                               __float2half_rn(p11 - __half2float(h11)));
            pal[kk][3] = pack2(__float2half_rn(p12 - __half2float(h12)),
                               __float2half_rn(p13 - __half2float(h13)));
        }

        // ---- O += P V : hi on fp32-acc, lo on fp16-acc flushed per tile ----
        const h16* vb = Vs + buf*VPL + g*VPAD + 2*t;
        uint32_t ol[16][2];
#pragma unroll
        for (int nt = 0; nt < 16; nt++) { ol[nt][0] = 0u; ol[nt][1] = 0u; }
#pragma unroll
        for (int kk = 0; kk < 4; kk++) {
            const int ko = kk * 16;
#pragma unroll
            for (int nt = 0; nt < 16; nt++) {
                uint32_t bh[2];
                const h16* pv = vb + nt*8*VPAD + ko;
                bh[0] = *(const uint32_t*)(pv);
                bh[1] = *(const uint32_t*)(pv + 8);
                mma_f16(o[nt], pah[kk], bh);
                mma_f16acc(ol[nt], pal[kk], bh);
            }
        }
#pragma unroll
        for (int nt = 0; nt < 16; nt++) add_f16acc(o[nt], ol[nt]);
        __syncthreads();
    }

    // epilogue: normalize, split, store fp16 hi/lo
    const float inv0 = lsum0 > 0.f ? 1.f / lsum0 : 0.f;
    const float inv1 = lsum1 > 0.f ? 1.f / lsum1 : 0.f;
    const int row0 = q0 + w*16 + g;
    const size_t base0 = (size_t)(b*L_ + row0) * D_ + h * HD_;
    const size_t base1 = base0 + 8 * (size_t)D_;

#pragma unroll
    for (int nt = 0; nt < 16; nt++) {
        const int col = nt*8 + 2*t;
        float v0 = o[nt][0] * inv0, v1 = o[nt][1] * inv0;
        float v2 = o[nt][2] * inv1, v3 = o[nt][3] * inv1;
        h16 h0 = __float2half_rn(v0), h1 = __float2half_rn(v1);
        h16 h2 = __float2half_rn(v2), h3 = __float2half_rn(v3);
        *(uint32_t*)(aoh + base0 + col) = pack2(h0, h1);
        *(uint32_t*)(aoh + base1 + col) = pack2(h2, h3);
        *(uint32_t*)(aol + base0 + col) =
            pack2(__float2half_rn(v0 - __half2float(h0)),
                  __float2half_rn(v1 - __half2float(h1)));
        *(uint32_t*)(aol + base1 + col) =
            pack2(__float2half_rn(v2 - __half2float(h2)),
                  __float2half_rn(v3 - __half2float(h3)));
    }
}

// ---------------------------------------------------------------------------
// Launch
// ---------------------------------------------------------------------------
extern "C" void kernel_launch(void* const* d_in, const int* in_sizes, int n_in,
                              void* d_out, int out_size) {
    const float* x    = (const float*)d_in[0];
    const int*   mask = (const int*)  d_in[1];
    const float* Wq   = (const float*)d_in[2];
    const float* Wk   = (const float*)d_in[3];
    const float* Wv   = (const float*)d_in[4];
    const float* Wo   = (const float*)d_in[5];
    const float* qg   = (const float*)d_in[6];
    const float* kg   = (const float*)d_in[7];
    float* out = (float*)d_out;

    float *q, *k, *v;
    h16 *xh, *xl, *wq, *wk, *wv, *wo;
    h16 *qhp, *qlp, *khp, *vtp, *aoh, *aol;
    cudaGetSymbolAddress((void**)&q,   g_q);
    cudaGetSymbolAddress((void**)&k,   g_k);
    cudaGetSymbolAddress((void**)&v,   g_v);
    cudaGetSymbolAddress((void**)&xh,  g_xh);  cudaGetSymbolAddress((void**)&xl,  g_xl);
    cudaGetSymbolAddress((void**)&wq,  g_wq);
    cudaGetSymbolAddress((void**)&wk,  g_wk);
    cudaGetSymbolAddress((void**)&wv,  g_wv);
    cudaGetSymbolAddress((void**)&wo,  g_wo);
    cudaGetSymbolAddress((void**)&qhp, g_qh);  cudaGetSymbolAddress((void**)&qlp, g_ql);
    cudaGetSymbolAddress((void**)&khp, g_kh);
    cudaGetSymbolAddress((void**)&vtp, g_vt);
    cudaGetSymbolAddress((void**)&aoh, g_aoh); cudaGetSymbolAddress((void**)&aol, g_aol);

    cudaFuncSetAttribute(k_gemm_bt, cudaFuncAttributeMaxDynamicSharedMemorySize, SMEM_TB_BYTES);
    cudaFuncSetAttribute(k_flash,   cudaFuncAttributeMaxDynamicSharedMemorySize, FA_SMEM_BYTES);

    const int M = B_ * L_;
    dim3 blk(256);

    auto launch_split = [&](const float* src, h16* hi, h16* lo, int n) {
        int n4 = n / 4;
        k_split<<<(n4 + 255) / 256, 256>>>((const float4*)src, (ushort4*)hi, (ushort4*)lo, n4);
    };
    auto launch_cvt = [&](const float* src, h16* hi, int n) {
        int n4 = n / 4;
        k_cvt<<<(n4 + 255) / 256, 256>>>((const float4*)src, (ushort4*)hi, n4);
    };

    // input split (2-term), weights single fp16
    launch_split(x, xh, xl, M * D_);
    launch_cvt(Wq, wq, D_ * D_);
    launch_cvt(Wk, wk, KVH_ * HD_ * D_);
    launch_cvt(Wv, wv, KVH_ * HD_ * D_);
    launch_cvt(Wo, wo, D_ * D_);

    // projections
    k_gemm_bt<<<dim3(D_/BN,         M/BM), blk, SMEM_TB_BYTES>>>(xh, xl, D_, wq, D_, q, D_,       D_);
    k_gemm_bt<<<dim3((KVH_*HD_)/BN, M/BM), blk, SMEM_TB_BYTES>>>(xh, xl, D_, wk, D_, k, KVH_*HD_, D_);
    k_gemm_bt<<<dim3((KVH_*HD_)/BN, M/BM), blk, SMEM_TB_BYTES>>>(xh, xl, D_, wv, D_, v, KVH_*HD_, D_);

    // rmsnorm + rope -> fp16 planes (q 2-term, k 1-term)
    rms_rope_split_kernel<<<(B_ * L_ * H_)   / 8, 256>>>(q, qg, qhp, qlp, H_);
    rms_rope_split_kernel<<<(B_ * L_ * KVH_) / 8, 256>>>(k, kg, khp, (h16*)nullptr, KVH_);

    // V transpose (single fp16)
    k_vtrans<<<dim3(L_/32, HD_/32, B_*KVH_), 256>>>(v, vtp);

    // fused flash attention -> ao fp16 hi/lo planes
    k_flash<<<dim3(L_/128, H_, B_), 256, FA_SMEM_BYTES>>>(qhp, qlp, khp, vtp,
                                                          mask, aoh, aol);

    // output projection
    k_gemm_bt<<<dim3(D_/BN, M/BM), blk, SMEM_TB_BYTES>>>(aoh, aol, D_, wo, D_, out, D_, D_);
}

// round 7
// speedup vs baseline: 1.1586x; 1.1586x over previous
#include <cuda_runtime.h>
#include <cuda_fp16.h>
#include <math.h>
#include <math_constants.h>
#include <stdint.h>

#define B_    2
#define L_    2048
#define D_    2048
#define H_    16
#define KVH_  4
#define HD_   128
#define EPS_  1e-6f

typedef __half h16;

// ---------------------------------------------------------------------------
// Static scratch
// ---------------------------------------------------------------------------
__device__ float g_q [B_*L_*D_];
__device__ float g_k [B_*L_*KVH_*HD_];
__device__ float g_v [B_*L_*KVH_*HD_];

__device__ h16 g_xh [B_*L_*D_],      g_xl [B_*L_*D_];
__device__ h16 g_wq [D_*D_];
__device__ h16 g_wk [KVH_*HD_*D_];
__device__ h16 g_wv [KVH_*HD_*D_];
__device__ h16 g_wo [D_*D_];
__device__ h16 g_qh [B_*L_*D_];
__device__ h16 g_kh [B_*L_*KVH_*HD_];
__device__ h16 g_vt [B_*KVH_*HD_*L_];                 // V transposed [b][kvh][d][L]
__device__ h16 g_aoh[B_*L_*D_],      g_aol[B_*L_*D_];

// ---------------------------------------------------------------------------
// PTX helpers
// ---------------------------------------------------------------------------
__device__ __forceinline__ void mma_f16(float* c, const uint32_t* a, const uint32_t* b) {
    asm volatile(
        "mma.sync.aligned.m16n8k16.row.col.f32.f16.f16.f32 "
        "{%0,%1,%2,%3}, {%4,%5,%6,%7}, {%8,%9}, {%0,%1,%2,%3};\n"
        : "+f"(c[0]), "+f"(c[1]), "+f"(c[2]), "+f"(c[3])
        : "r"(a[0]), "r"(a[1]), "r"(a[2]), "r"(a[3]), "r"(b[0]), "r"(b[1]));
}

__device__ __forceinline__ void cp16(const h16* dst_s, const h16* src_g) {
    uint32_t d = (uint32_t)__cvta_generic_to_shared(dst_s);
    asm volatile("cp.async.cg.shared.global [%0], [%1], 16;\n"
                 :: "r"(d), "l"(src_g) : "memory");
}
__device__ __forceinline__ void cp_commit() {
    asm volatile("cp.async.commit_group;\n" ::: "memory");
}
template<int N>
__device__ __forceinline__ void cp_wait() {
    asm volatile("cp.async.wait_group %0;\n" :: "n"(N) : "memory");
}

__device__ __forceinline__ uint32_t pack2(h16 a, h16 b) {
    uint32_t x = *reinterpret_cast<unsigned short*>(&a);
    uint32_t y = *reinterpret_cast<unsigned short*>(&b);
    return x | (y << 16);
}

__device__ __forceinline__ void split1(float x, unsigned short& h, unsigned short& l) {
    h16 hh = __float2half_rn(x);
    h16 ll = __float2half_rn(x - __half2float(hh));
    h = *reinterpret_cast<unsigned short*>(&hh);
    l = *reinterpret_cast<unsigned short*>(&ll);
}

// ---------------------------------------------------------------------------
// Projection GEMM: C[M,N] fp32 = (Ah+Al)[M,K] * Bh[N,K]^T, fp16 2-product
// (identical to round-5 version — that was the fastest projection config)
// ---------------------------------------------------------------------------
#define BM 128
#define BN 128
#define BK 32
#define APAD 40

#define SM_A_HALVES (2*2*BM*APAD)
#define SM_B_HALVES (2*BN*APAD)
#define SMEM_TB_BYTES ((SM_A_HALVES + SM_B_HALVES)*2)   // 61440

__global__ __launch_bounds__(256, 1)
void k_gemm_bt(const h16* __restrict__ Ah, const h16* __restrict__ Al, int lda,
               const h16* __restrict__ Bh, int ldb,
               float* __restrict__ C, int ldc, int K)
{
    extern __shared__ h16 sh[];
    h16* sA = sh;
    h16* sB = sh + SM_A_HALVES;

    const int tid = threadIdx.x;
    const int m0 = blockIdx.y * BM;
    const int n0 = blockIdx.x * BN;

    const h16* Ap[2] = { Ah + (size_t)m0 * lda, Al + (size_t)m0 * lda };
    const h16* Bp    =   Bh + (size_t)n0 * ldb;

    const int lane = tid & 31;
    const int g    = lane >> 2;
    const int t    = lane & 3;
    const int warp = tid >> 5;
    const int wm   = warp >> 2;
    const int wn   = warp & 3;

    float acc[4][4][4];
#pragma unroll
    for (int i = 0; i < 4; i++)
#pragma unroll
        for (int j = 0; j < 4; j++)
#pragma unroll
            for (int c = 0; c < 4; c++) acc[i][j][c] = 0.f;

    auto load_stage = [&](int s, int k0) {
#pragma unroll
        for (int p = 0; p < 2; p++) {
#pragma unroll
            for (int i = 0; i < 2; i++) {
                int c   = tid + i * 256;
                int row = c >> 2, kc = c & 3;
                cp16(sA + (size_t)(s*2+p)*BM*APAD + row*APAD + kc*8,
                     Ap[p] + (size_t)row * lda + k0 + kc*8);
            }
        }
#pragma unroll
        for (int i = 0; i < 2; i++) {
            int c   = tid + i * 256;
            int row = c >> 2, kc = c & 3;
            cp16(sB + (size_t)s*BN*APAD + row*APAD + kc*8,
                 Bp + (size_t)row * ldb + k0 + kc*8);
        }
    };

    const int nk = K / BK;
    load_stage(0, 0);
    cp_commit();

    for (int ks = 0; ks < nk; ks++) {
        const int buf = ks & 1;
        if (ks + 1 < nk) {
            load_stage(buf ^ 1, (ks + 1) * BK);
            cp_commit();
            cp_wait<1>();
        } else {
            cp_wait<0>();
        }
        __syncthreads();

        const h16* sAh = sA + (size_t)(buf*2+0)*BM*APAD;
        const h16* sAl = sA + (size_t)(buf*2+1)*BM*APAD;
        const h16* sBh = sB + (size_t)buf*BN*APAD;

#pragma unroll
        for (int kk = 0; kk < 2; kk++) {
            const int ko = kk * 16;

            uint32_t ah[4][4], alr[4][4];
#pragma unroll
            for (int mt = 0; mt < 4; mt++) {
                const int r = wm*64 + mt*16 + g;
                const h16* p0 = sAh + r*APAD + ko + 2*t;
                ah[mt][0] = *(const uint32_t*)(p0);
                ah[mt][1] = *(const uint32_t*)(p0 + 8*APAD);
                ah[mt][2] = *(const uint32_t*)(p0 + 8);
                ah[mt][3] = *(const uint32_t*)(p0 + 8*APAD + 8);
                const h16* p1 = sAl + r*APAD + ko + 2*t;
                alr[mt][0] = *(const uint32_t*)(p1);
                alr[mt][1] = *(const uint32_t*)(p1 + 8*APAD);
                alr[mt][2] = *(const uint32_t*)(p1 + 8);
                alr[mt][3] = *(const uint32_t*)(p1 + 8*APAD + 8);
            }

            uint32_t bh[4][2];
#pragma unroll
            for (int nt = 0; nt < 4; nt++) {
                const int n = wn*32 + nt*8 + g;
                const h16* p0 = sBh + n*APAD + ko + 2*t;
                bh[nt][0] = *(const uint32_t*)(p0);
                bh[nt][1] = *(const uint32_t*)(p0 + 8);
            }

#pragma unroll
            for (int mt = 0; mt < 4; mt++)
#pragma unroll
                for (int nt = 0; nt < 4; nt++) {
                    mma_f16(acc[mt][nt], ah[mt],  bh[nt]);
                    mma_f16(acc[mt][nt], alr[mt], bh[nt]);
                }
        }
        __syncthreads();
    }

#pragma unroll
    for (int mt = 0; mt < 4; mt++) {
        const int r = m0 + wm*64 + mt*16 + g;
#pragma unroll
        for (int nt = 0; nt < 4; nt++) {
            const int c = n0 + wn*32 + nt*8 + 2*t;
            *reinterpret_cast<float2*>(&C[(size_t)r     * ldc + c]) =
                make_float2(acc[mt][nt][0], acc[mt][nt][1]);
            *reinterpret_cast<float2*>(&C[(size_t)(r+8) * ldc + c]) =
                make_float2(acc[mt][nt][2], acc[mt][nt][3]);
        }
    }
}

// ---------------------------------------------------------------------------
// fp32 -> (hi, lo) fp16 split  /  fp32 -> fp16 convert
// ---------------------------------------------------------------------------
__global__ void k_split(const float4* __restrict__ X,
                        ushort4* __restrict__ Hi, ushort4* __restrict__ Lo, int n4)
{
    int i = blockIdx.x * blockDim.x + threadIdx.x;
    if (i >= n4) return;
    float4 v = X[i];
    ushort4 hv, lv;
    split1(v.x, hv.x, lv.x);
    split1(v.y, hv.y, lv.y);
    split1(v.z, hv.z, lv.z);
    split1(v.w, hv.w, lv.w);
    Hi[i] = hv;
    Lo[i] = lv;
}

__global__ void k_cvt(const float4* __restrict__ X, ushort4* __restrict__ Hi, int n4)
{
    int i = blockIdx.x * blockDim.x + threadIdx.x;
    if (i >= n4) return;
    float4 v = X[i];
    h16 a = __float2half_rn(v.x), b = __float2half_rn(v.y);
    h16 c = __float2half_rn(v.z), d = __float2half_rn(v.w);
    ushort4 hv;
    hv.x = *reinterpret_cast<unsigned short*>(&a);
    hv.y = *reinterpret_cast<unsigned short*>(&b);
    hv.z = *reinterpret_cast<unsigned short*>(&c);
    hv.w = *reinterpret_cast<unsigned short*>(&d);
    Hi[i] = hv;
}

// ---------------------------------------------------------------------------
// RMSNorm + RoPE, fp32 in -> fp16 plane. One warp per (b,l,h).
// ---------------------------------------------------------------------------
__global__ void rms_rope_kernel(const float* __restrict__ X,
                                const float* __restrict__ gamma,
                                h16* __restrict__ Xh, int heads) {
    const int warp = (blockIdx.x * blockDim.x + threadIdx.x) >> 5;
    const int lane = threadIdx.x & 31;
    const int h = warp % heads;
    const int l = (warp / heads) % L_;
    const int b = warp / (heads * L_);

    const size_t base = ((size_t)(b * L_ + l) * heads + h) * HD_;
    const float* vec = X + base;

    const int p0 = lane, p1 = lane + 32;
    float x0a = vec[2*p0],   x1a = vec[2*p0+1];
    float x0b = vec[2*p1],   x1b = vec[2*p1+1];

    float ss = x0a*x0a + x1a*x1a + x0b*x0b + x1b*x1b;
#pragma unroll
    for (int off = 16; off; off >>= 1)
        ss += __shfl_xor_sync(0xffffffffu, ss, off);

    const float inv = rsqrtf(ss * (1.0f / HD_) + EPS_);
    const float LOG2_THETA = 13.287712379549449f;
    const float fl = (float)l;

    {
        float g0 = gamma[2*p0], g1 = gamma[2*p0+1];
        float re = x0a * inv * g0, im = x1a * inv * g1;
        float fr = fl * exp2f(-(2.0f * p0 / (float)HD_) * LOG2_THETA);
        float s, c; sincosf(fr, &s, &c);
        Xh[base + 2*p0]   = __float2half_rn(re * c - im * s);
        Xh[base + 2*p0+1] = __float2half_rn(re * s + im * c);
    }
    {
        float g0 = gamma[2*p1], g1 = gamma[2*p1+1];
        float re = x0b * inv * g0, im = x1b * inv * g1;
        float fr = fl * exp2f(-(2.0f * p1 / (float)HD_) * LOG2_THETA);
        float s, c; sincosf(fr, &s, &c);
        Xh[base + 2*p1]   = __float2half_rn(re * c - im * s);
        Xh[base + 2*p1+1] = __float2half_rn(re * s + im * c);
    }
}

// ---------------------------------------------------------------------------
// V transpose: v fp32 [b][l][kvh][d] -> vt fp16 [b][kvh][d][L]
// ---------------------------------------------------------------------------
__global__ void k_vtrans(const float* __restrict__ V, h16* __restrict__ Vt)
{
    __shared__ float tile[32][33];
    const int tx = threadIdx.x & 31;
    const int ty = threadIdx.x >> 5;
    const int l0 = blockIdx.x * 32;
    const int d0 = blockIdx.y * 32;
    const int z  = blockIdx.z;
    const int b  = z >> 2, kvh = z & 3;

#pragma unroll
    for (int i = 0; i < 4; i++) {
        int l = l0 + ty + i*8;
        tile[ty + i*8][tx] =
            V[((size_t)(b*L_ + l) * KVH_ + kvh) * HD_ + d0 + tx];
    }
    __syncthreads();
#pragma unroll
    for (int i = 0; i < 4; i++) {
        int d = d0 + ty + i*8;
        h16 val = __float2half_rn(tile[tx][ty + i*8]);
        size_t idx = ((size_t)(b*KVH_ + kvh) * HD_ + d) * L_ + l0 + tx;
        Vt[idx] = val;
    }
}

// ---------------------------------------------------------------------------
// Fused flash attention, single-product fp16 MMA (fp32 accumulate).
// Block: (q-tile 128, head, batch). 256 threads = 8 warps, 16 q-rows each.
// ---------------------------------------------------------------------------
#define QPAD 136
#define VPAD 72

#define QPL  (128*QPAD)           // 17408
#define KPL  (64*QPAD)            // 8704
#define VPL  (128*VPAD)           // 9216
#define QS_OFF 0
#define KS_OFF QPL                // single Q plane now
#define VS_OFF (KS_OFF + 2*KPL)
#define MS_OFF_H (VS_OFF + 2*VPL)
#define FA_SMEM_BYTES (MS_OFF_H*2 + 2*64*4)   // ~107KB

__global__ __launch_bounds__(256, 1)
void k_flash(const h16* __restrict__ qh,
             const h16* __restrict__ kh,
             const h16* __restrict__ vt,
             const int* __restrict__ mask,
             h16* __restrict__ aoh, h16* __restrict__ aol)
{
    extern __shared__ h16 sm[];
    h16*   Qs = sm + QS_OFF;
    h16*   Ks = sm + KS_OFF;
    h16*   Vs = sm + VS_OFF;
    float* Ms = (float*)(sm + MS_OFF_H);

    const int tid  = threadIdx.x;
    const int lane = tid & 31;
    const int g    = lane >> 2;
    const int t    = lane & 3;
    const int w    = tid >> 5;

    const int qt = blockIdx.x, h = blockIdx.y, b = blockIdx.z;
    const int kvh = h >> 2;
    const int q0  = qt * 128;

    const h16* Qg = qh + ((size_t)(b*L_ + q0)) * D_ + h * HD_;
    const h16* Kg = kh + ((size_t)(b*L_)) * (KVH_*HD_) + kvh * HD_;
    const h16* Vg = vt + ((size_t)(b*KVH_ + kvh)) * HD_ * L_;

    // Q load (once): 128 rows x 16 chunks
#pragma unroll
    for (int i = 0; i < 8; i++) {
        int c = tid + i * 256;
        int row = c >> 4, ch = c & 15;
        cp16(Qs + row*QPAD + ch*8, Qg + (size_t)row * D_ + ch*8);
    }

    auto load_stage = [&](int s, int kt) {
        const int j0 = kt * 64;
#pragma unroll
        for (int i = 0; i < 4; i++) {          // K: 64 rows x 16 chunks
            int c = tid + i * 256;
            int row = c >> 4, ch = c & 15;
            cp16(Ks + s*KPL + row*QPAD + ch*8,
                 Kg + (size_t)(j0 + row) * (KVH_*HD_) + ch*8);
        }
#pragma unroll
        for (int i = 0; i < 4; i++) {          // V: 128 rows x 8 chunks
            int c = tid + i * 256;
            int row = c >> 3, ch = c & 7;
            cp16(Vs + s*VPL + row*VPAD + ch*8,
                 Vg + (size_t)row * L_ + j0 + ch*8);
        }
        if (tid < 64)
            Ms[s*64 + tid] = mask[b*L_ + j0 + tid] ? 0.f : -1e30f;
    };

    load_stage(0, 0);
    cp_commit();

    float o[16][4];
#pragma unroll
    for (int i = 0; i < 16; i++)
#pragma unroll
        for (int c = 0; c < 4; c++) o[i][c] = 0.f;

    float mprev0 = -1e30f, mprev1 = -1e30f;
    float lsum0 = 0.f, lsum1 = 0.f;
    const float sc = 0.08838834764831845f;

    const int NT_ = L_ / 64;
    for (int kt = 0; kt < NT_; kt++) {
        const int buf = kt & 1;
        if (kt + 1 < NT_) {
            load_stage(buf ^ 1, kt + 1);
            cp_commit();
            cp_wait<1>();
        } else {
            cp_wait<0>();
        }
        __syncthreads();

        // ---- S = Q K^T : per warp m16 x n64 x k128, single product ----
        float s[8][4];
#pragma unroll
        for (int nt = 0; nt < 8; nt++)
#pragma unroll
            for (int c = 0; c < 4; c++) s[nt][c] = 0.f;

        const h16* qb = Qs + (w*16 + g)*QPAD + 2*t;
        const h16* kb = Ks + buf*KPL + g*QPAD + 2*t;

#pragma unroll
        for (int kk = 0; kk < 8; kk++) {
            const int ko = kk * 16;
            uint32_t ah[4];
            ah[0] = *(const uint32_t*)(qb + ko);
            ah[1] = *(const uint32_t*)(qb + ko + 8*QPAD);
            ah[2] = *(const uint32_t*)(qb + ko + 8);
            ah[3] = *(const uint32_t*)(qb + ko + 8*QPAD + 8);
#pragma unroll
            for (int nt = 0; nt < 8; nt++) {
                uint32_t bh[2];
                const h16* pk = kb + nt*8*QPAD + ko;
                bh[0] = *(const uint32_t*)(pk);
                bh[1] = *(const uint32_t*)(pk + 8);
                mma_f16(s[nt], ah, bh);
            }
        }

        // ---- online softmax on fragments ----
        const float* msf = Ms + buf*64;
        float m0 = -1e30f, m1 = -1e30f;
#pragma unroll
        for (int nt = 0; nt < 8; nt++) {
            float b0 = msf[8*nt + 2*t], b1 = msf[8*nt + 2*t + 1];
            s[nt][0] = s[nt][0]*sc + b0;
            s[nt][1] = s[nt][1]*sc + b1;
            s[nt][2] = s[nt][2]*sc + b0;
            s[nt][3] = s[nt][3]*sc + b1;
            m0 = fmaxf(m0, fmaxf(s[nt][0], s[nt][1]));
            m1 = fmaxf(m1, fmaxf(s[nt][2], s[nt][3]));
        }
        m0 = fmaxf(m0, __shfl_xor_sync(0xffffffffu, m0, 1));
        m0 = fmaxf(m0, __shfl_xor_sync(0xffffffffu, m0, 2));
        m1 = fmaxf(m1, __shfl_xor_sync(0xffffffffu, m1, 1));
        m1 = fmaxf(m1, __shfl_xor_sync(0xffffffffu, m1, 2));

        const float mn0 = fmaxf(mprev0, m0);
        const float mn1 = fmaxf(mprev1, m1);
        const float alpha0 = __expf(mprev0 - mn0);
        const float alpha1 = __expf(mprev1 - mn1);
        mprev0 = mn0; mprev1 = mn1;

        float sum0 = 0.f, sum1 = 0.f;
#pragma unroll
        for (int nt = 0; nt < 8; nt++) {
            s[nt][0] = __expf(s[nt][0] - mn0);
            s[nt][1] = __expf(s[nt][1] - mn0);
            s[nt][2] = __expf(s[nt][2] - mn1);
            s[nt][3] = __expf(s[nt][3] - mn1);
            sum0 += s[nt][0] + s[nt][1];
            sum1 += s[nt][2] + s[nt][3];
        }
        sum0 += __shfl_xor_sync(0xffffffffu, sum0, 1);
        sum0 += __shfl_xor_sync(0xffffffffu, sum0, 2);
        sum1 += __shfl_xor_sync(0xffffffffu, sum1, 1);
        sum1 += __shfl_xor_sync(0xffffffffu, sum1, 2);
        lsum0 = lsum0 * alpha0 + sum0;
        lsum1 = lsum1 * alpha1 + sum1;

#pragma unroll
        for (int nt = 0; nt < 16; nt++) {
            o[nt][0] *= alpha0; o[nt][1] *= alpha0;
            o[nt][2] *= alpha1; o[nt][3] *= alpha1;
        }

        // ---- P fragments (round to fp16, no split) ----
        uint32_t pah[4][4];
#pragma unroll
        for (int kk = 0; kk < 4; kk++) {
            const int n0t = 2*kk, n1t = 2*kk + 1;
            pah[kk][0] = pack2(__float2half_rn(s[n0t][0]), __float2half_rn(s[n0t][1]));
            pah[kk][1] = pack2(__float2half_rn(s[n0t][2]), __float2half_rn(s[n0t][3]));
            pah[kk][2] = pack2(__float2half_rn(s[n1t][0]), __float2half_rn(s[n1t][1]));
            pah[kk][3] = pack2(__float2half_rn(s[n1t][2]), __float2half_rn(s[n1t][3]));
        }

        // ---- O += P V : per warp m16 x n128 x k64, single product ----
        const h16* vb = Vs + buf*VPL + g*VPAD + 2*t;
#pragma unroll
        for (int kk = 0; kk < 4; kk++) {
            const int ko = kk * 16;
#pragma unroll
            for (int nt = 0; nt < 16; nt++) {
                uint32_t bh[2];
                const h16* pv = vb + nt*8*VPAD + ko;
                bh[0] = *(const uint32_t*)(pv);
                bh[1] = *(const uint32_t*)(pv + 8);
                mma_f16(o[nt], pah[kk], bh);
            }
        }
        __syncthreads();
    }

    // epilogue: normalize, split, store fp16 hi/lo (for O projection input)
    const float inv0 = lsum0 > 0.f ? 1.f / lsum0 : 0.f;
    const float inv1 = lsum1 > 0.f ? 1.f / lsum1 : 0.f;
    const int row0 = q0 + w*16 + g;
    const size_t base0 = (size_t)(b*L_ + row0) * D_ + h * HD_;
    const size_t base1 = base0 + 8 * (size_t)D_;

#pragma unroll
    for (int nt = 0; nt < 16; nt++) {
        const int col = nt*8 + 2*t;
        float v0 = o[nt][0] * inv0, v1 = o[nt][1] * inv0;
        float v2 = o[nt][2] * inv1, v3 = o[nt][3] * inv1;
        h16 h0 = __float2half_rn(v0), h1 = __float2half_rn(v1);
        h16 h2 = __float2half_rn(v2), h3 = __float2half_rn(v3);
        *(uint32_t*)(aoh + base0 + col) = pack2(h0, h1);
        *(uint32_t*)(aoh + base1 + col) = pack2(h2, h3);
        *(uint32_t*)(aol + base0 + col) =
            pack2(__float2half_rn(v0 - __half2float(h0)),
                  __float2half_rn(v1 - __half2float(h1)));
        *(uint32_t*)(aol + base1 + col) =
            pack2(__float2half_rn(v2 - __half2float(h2)),
                  __float2half_rn(v3 - __half2float(h3)));
    }
}

// ---------------------------------------------------------------------------
// Launch
// ---------------------------------------------------------------------------
extern "C" void kernel_launch(void* const* d_in, const int* in_sizes, int n_in,
                              void* d_out, int out_size) {
    const float* x    = (const float*)d_in[0];
    const int*   mask = (const int*)  d_in[1];
    const float* Wq   = (const float*)d_in[2];
    const float* Wk   = (const float*)d_in[3];
    const float* Wv   = (const float*)d_in[4];
    const float* Wo   = (const float*)d_in[5];
    const float* qg   = (const float*)d_in[6];
    const float* kg   = (const float*)d_in[7];
    float* out = (float*)d_out;

    float *q, *k, *v;
    h16 *xh, *xl, *wq, *wk, *wv, *wo;
    h16 *qhp, *khp, *vtp, *aoh, *aol;
    cudaGetSymbolAddress((void**)&q,   g_q);
    cudaGetSymbolAddress((void**)&k,   g_k);
    cudaGetSymbolAddress((void**)&v,   g_v);
    cudaGetSymbolAddress((void**)&xh,  g_xh);  cudaGetSymbolAddress((void**)&xl,  g_xl);
    cudaGetSymbolAddress((void**)&wq,  g_wq);
    cudaGetSymbolAddress((void**)&wk,  g_wk);
    cudaGetSymbolAddress((void**)&wv,  g_wv);
    cudaGetSymbolAddress((void**)&wo,  g_wo);
    cudaGetSymbolAddress((void**)&qhp, g_qh);
    cudaGetSymbolAddress((void**)&khp, g_kh);
    cudaGetSymbolAddress((void**)&vtp, g_vt);
    cudaGetSymbolAddress((void**)&aoh, g_aoh); cudaGetSymbolAddress((void**)&aol, g_aol);

    cudaFuncSetAttribute(k_gemm_bt, cudaFuncAttributeMaxDynamicSharedMemorySize, SMEM_TB_BYTES);
    cudaFuncSetAttribute(k_flash,   cudaFuncAttributeMaxDynamicSharedMemorySize, FA_SMEM_BYTES);

    const int M = B_ * L_;
    dim3 blk(256);

    auto launch_split = [&](const float* src, h16* hi, h16* lo, int n) {
        int n4 = n / 4;
        k_split<<<(n4 + 255) / 256, 256>>>((const float4*)src, (ushort4*)hi, (ushort4*)lo, n4);
    };
    auto launch_cvt = [&](const float* src, h16* hi, int n) {
        int n4 = n / 4;
        k_cvt<<<(n4 + 255) / 256, 256>>>((const float4*)src, (ushort4*)hi, n4);
    };

    // input split (2-term), weights single fp16
    launch_split(x, xh, xl, M * D_);
    launch_cvt(Wq, wq, D_ * D_);
    launch_cvt(Wk, wk, KVH_ * HD_ * D_);
    launch_cvt(Wv, wv, KVH_ * HD_ * D_);
    launch_cvt(Wo, wo, D_ * D_);

    // projections (fp16 2-product tensor-core GEMM)
    k_gemm_bt<<<dim3(D_/BN,         M/BM), blk, SMEM_TB_BYTES>>>(xh, xl, D_, wq, D_, q, D_,       D_);
    k_gemm_bt<<<dim3((KVH_*HD_)/BN, M/BM), blk, SMEM_TB_BYTES>>>(xh, xl, D_, wk, D_, k, KVH_*HD_, D_);
    k_gemm_bt<<<dim3((KVH_*HD_)/BN, M/BM), blk, SMEM_TB_BYTES>>>(xh, xl, D_, wv, D_, v, KVH_*HD_, D_);

    // rmsnorm + rope -> single fp16 planes
    rms_rope_kernel<<<(B_ * L_ * H_)   / 8, 256>>>(q, qg, qhp, H_);
    rms_rope_kernel<<<(B_ * L_ * KVH_) / 8, 256>>>(k, kg, khp, KVH_);

    // V transpose (single fp16)
    k_vtrans<<<dim3(L_/32, HD_/32, B_*KVH_), 256>>>(v, vtp);

    // fused flash attention (single-product) -> ao fp16 hi/lo planes
    k_flash<<<dim3(L_/128, H_, B_), 256, FA_SMEM_BYTES>>>(qhp, khp, vtp,
                                                          mask, aoh, aol);

    // output projection (2-product)
    k_gemm_bt<<<dim3(D_/BN, M/BM), blk, SMEM_TB_BYTES>>>(aoh, aol, D_, wo, D_, out, D_, D_);
}

// round 8
// speedup vs baseline: 1.5550x; 1.3421x over previous
#include <cuda_runtime.h>
#include <cuda_fp16.h>
#include <math.h>
#include <math_constants.h>
#include <stdint.h>

#define B_    2
#define L_    2048
#define D_    2048
#define H_    16
#define KVH_  4
#define HD_   128
#define EPS_  1e-6f

typedef __half h16;

// ---------------------------------------------------------------------------
// Static scratch
// ---------------------------------------------------------------------------
__device__ float g_q [B_*L_*D_];
__device__ float g_k [B_*L_*KVH_*HD_];
__device__ float g_v [B_*L_*KVH_*HD_];

__device__ h16 g_xh [B_*L_*D_];
__device__ h16 g_wq [D_*D_];
__device__ h16 g_wk [KVH_*HD_*D_];
__device__ h16 g_wv [KVH_*HD_*D_];
__device__ h16 g_wo [D_*D_];
__device__ h16 g_qh [B_*L_*D_];
__device__ h16 g_kh [B_*L_*KVH_*HD_];
__device__ h16 g_vt [B_*KVH_*HD_*L_];                 // V transposed [b][kvh][d][L]
__device__ h16 g_ao [B_*L_*D_];

// ---------------------------------------------------------------------------
// PTX helpers
// ---------------------------------------------------------------------------
__device__ __forceinline__ void mma_f16(float* c, const uint32_t* a, const uint32_t* b) {
    asm volatile(
        "mma.sync.aligned.m16n8k16.row.col.f32.f16.f16.f32 "
        "{%0,%1,%2,%3}, {%4,%5,%6,%7}, {%8,%9}, {%0,%1,%2,%3};\n"
        : "+f"(c[0]), "+f"(c[1]), "+f"(c[2]), "+f"(c[3])
        : "r"(a[0]), "r"(a[1]), "r"(a[2]), "r"(a[3]), "r"(b[0]), "r"(b[1]));
}

__device__ __forceinline__ void cp16(const h16* dst_s, const h16* src_g) {
    uint32_t d = (uint32_t)__cvta_generic_to_shared(dst_s);
    asm volatile("cp.async.cg.shared.global [%0], [%1], 16;\n"
                 :: "r"(d), "l"(src_g) : "memory");
}
__device__ __forceinline__ void cp_commit() {
    asm volatile("cp.async.commit_group;\n" ::: "memory");
}
template<int N>
__device__ __forceinline__ void cp_wait() {
    asm volatile("cp.async.wait_group %0;\n" :: "n"(N) : "memory");
}

__device__ __forceinline__ uint32_t pack2(h16 a, h16 b) {
    uint32_t x = *reinterpret_cast<unsigned short*>(&a);
    uint32_t y = *reinterpret_cast<unsigned short*>(&b);
    return x | (y << 16);
}

// ---------------------------------------------------------------------------
// Projection GEMM: C[M,N] fp32 = A[M,K] * B[N,K]^T, pure fp16, fp32 acc.
// 128x128 tile, BK=32, 256 threads (8 warps = 2x4), double-buffered cp.async.
// ---------------------------------------------------------------------------
#define BM 128
#define BN 128
#define BK 32
#define APAD 40

#define SM_A_HALVES (2*BM*APAD)
#define SM_B_HALVES (2*BN*APAD)
#define SMEM_TB_BYTES ((SM_A_HALVES + SM_B_HALVES)*2)   // 40960

__global__ __launch_bounds__(256, 1)
void k_gemm_bt1(const h16* __restrict__ A, int lda,
                const h16* __restrict__ Bh, int ldb,
                float* __restrict__ C, int ldc, int K)
{
    extern __shared__ h16 sh[];
    h16* sA = sh;
    h16* sB = sh + SM_A_HALVES;

    const int tid = threadIdx.x;
    const int m0 = blockIdx.y * BM;
    const int n0 = blockIdx.x * BN;

    const h16* Ap = A  + (size_t)m0 * lda;
    const h16* Bp = Bh + (size_t)n0 * ldb;

    const int lane = tid & 31;
    const int g    = lane >> 2;
    const int t    = lane & 3;
    const int warp = tid >> 5;
    const int wm   = warp >> 2;
    const int wn   = warp & 3;

    float acc[4][4][4];
#pragma unroll
    for (int i = 0; i < 4; i++)
#pragma unroll
        for (int j = 0; j < 4; j++)
#pragma unroll
            for (int c = 0; c < 4; c++) acc[i][j][c] = 0.f;

    auto load_stage = [&](int s, int k0) {
#pragma unroll
        for (int i = 0; i < 2; i++) {
            int c   = tid + i * 256;
            int row = c >> 2, kc = c & 3;
            cp16(sA + (size_t)s*BM*APAD + row*APAD + kc*8,
                 Ap + (size_t)row * lda + k0 + kc*8);
        }
#pragma unroll
        for (int i = 0; i < 2; i++) {
            int c   = tid + i * 256;
            int row = c >> 2, kc = c & 3;
            cp16(sB + (size_t)s*BN*APAD + row*APAD + kc*8,
                 Bp + (size_t)row * ldb + k0 + kc*8);
        }
    };

    const int nk = K / BK;
    load_stage(0, 0);
    cp_commit();

    for (int ks = 0; ks < nk; ks++) {
        const int buf = ks & 1;
        if (ks + 1 < nk) {
            load_stage(buf ^ 1, (ks + 1) * BK);
            cp_commit();
            cp_wait<1>();
        } else {
            cp_wait<0>();
        }
        __syncthreads();

        const h16* sAb = sA + (size_t)buf*BM*APAD;
        const h16* sBb = sB + (size_t)buf*BN*APAD;

#pragma unroll
        for (int kk = 0; kk < 2; kk++) {
            const int ko = kk * 16;

            uint32_t ah[4][4];
#pragma unroll
            for (int mt = 0; mt < 4; mt++) {
                const int r = wm*64 + mt*16 + g;
                const h16* p0 = sAb + r*APAD + ko + 2*t;
                ah[mt][0] = *(const uint32_t*)(p0);
                ah[mt][1] = *(const uint32_t*)(p0 + 8*APAD);
                ah[mt][2] = *(const uint32_t*)(p0 + 8);
                ah[mt][3] = *(const uint32_t*)(p0 + 8*APAD + 8);
            }

            uint32_t bh[4][2];
#pragma unroll
            for (int nt = 0; nt < 4; nt++) {
                const int n = wn*32 + nt*8 + g;
                const h16* p0 = sBb + n*APAD + ko + 2*t;
                bh[nt][0] = *(const uint32_t*)(p0);
                bh[nt][1] = *(const uint32_t*)(p0 + 8);
            }

#pragma unroll
            for (int mt = 0; mt < 4; mt++)
#pragma unroll
                for (int nt = 0; nt < 4; nt++)
                    mma_f16(acc[mt][nt], ah[mt], bh[nt]);
        }
        __syncthreads();
    }

#pragma unroll
    for (int mt = 0; mt < 4; mt++) {
        const int r = m0 + wm*64 + mt*16 + g;
#pragma unroll
        for (int nt = 0; nt < 4; nt++) {
            const int c = n0 + wn*32 + nt*8 + 2*t;
            *reinterpret_cast<float2*>(&C[(size_t)r     * ldc + c]) =
                make_float2(acc[mt][nt][0], acc[mt][nt][1]);
            *reinterpret_cast<float2*>(&C[(size_t)(r+8) * ldc + c]) =
                make_float2(acc[mt][nt][2], acc[mt][nt][3]);
        }
    }
}

// ---------------------------------------------------------------------------
// fp32 -> fp16 convert
// ---------------------------------------------------------------------------
__global__ void k_cvt(const float4* __restrict__ X, ushort4* __restrict__ Hi, int n4)
{
    int i = blockIdx.x * blockDim.x + threadIdx.x;
    if (i >= n4) return;
    float4 v = X[i];
    h16 a = __float2half_rn(v.x), b = __float2half_rn(v.y);
    h16 c = __float2half_rn(v.z), d = __float2half_rn(v.w);
    ushort4 hv;
    hv.x = *reinterpret_cast<unsigned short*>(&a);
    hv.y = *reinterpret_cast<unsigned short*>(&b);
    hv.z = *reinterpret_cast<unsigned short*>(&c);
    hv.w = *reinterpret_cast<unsigned short*>(&d);
    Hi[i] = hv;
}

// ---------------------------------------------------------------------------
// RMSNorm + RoPE, fp32 in -> fp16 plane. One warp per (b,l,h).
// ---------------------------------------------------------------------------
__global__ void rms_rope_kernel(const float* __restrict__ X,
                                const float* __restrict__ gamma,
                                h16* __restrict__ Xh, int heads) {
    const int warp = (blockIdx.x * blockDim.x + threadIdx.x) >> 5;
    const int lane = threadIdx.x & 31;
    const int h = warp % heads;
    const int l = (warp / heads) % L_;
    const int b = warp / (heads * L_);

    const size_t base = ((size_t)(b * L_ + l) * heads + h) * HD_;
    const float* vec = X + base;

    const int p0 = lane, p1 = lane + 32;
    float x0a = vec[2*p0],   x1a = vec[2*p0+1];
    float x0b = vec[2*p1],   x1b = vec[2*p1+1];

    float ss = x0a*x0a + x1a*x1a + x0b*x0b + x1b*x1b;
#pragma unroll
    for (int off = 16; off; off >>= 1)
        ss += __shfl_xor_sync(0xffffffffu, ss, off);

    const float inv = rsqrtf(ss * (1.0f / HD_) + EPS_);
    const float LOG2_THETA = 13.287712379549449f;
    const float fl = (float)l;

    {
        float g0 = gamma[2*p0], g1 = gamma[2*p0+1];
        float re = x0a * inv * g0, im = x1a * inv * g1;
        float fr = fl * exp2f(-(2.0f * p0 / (float)HD_) * LOG2_THETA);
        float s, c; sincosf(fr, &s, &c);
        Xh[base + 2*p0]   = __float2half_rn(re * c - im * s);
        Xh[base + 2*p0+1] = __float2half_rn(re * s + im * c);
    }
    {
        float g0 = gamma[2*p1], g1 = gamma[2*p1+1];
        float re = x0b * inv * g0, im = x1b * inv * g1;
        float fr = fl * exp2f(-(2.0f * p1 / (float)HD_) * LOG2_THETA);
        float s, c; sincosf(fr, &s, &c);
        Xh[base + 2*p1]   = __float2half_rn(re * c - im * s);
        Xh[base + 2*p1+1] = __float2half_rn(re * s + im * c);
    }
}

// ---------------------------------------------------------------------------
// V transpose: v fp32 [b][l][kvh][d] -> vt fp16 [b][kvh][d][L]
// ---------------------------------------------------------------------------
__global__ void k_vtrans(const float* __restrict__ V, h16* __restrict__ Vt)
{
    __shared__ float tile[32][33];
    const int tx = threadIdx.x & 31;
    const int ty = threadIdx.x >> 5;
    const int l0 = blockIdx.x * 32;
    const int d0 = blockIdx.y * 32;
    const int z  = blockIdx.z;
    const int b  = z >> 2, kvh = z & 3;

#pragma unroll
    for (int i = 0; i < 4; i++) {
        int l = l0 + ty + i*8;
        tile[ty + i*8][tx] =
            V[((size_t)(b*L_ + l) * KVH_ + kvh) * HD_ + d0 + tx];
    }
    __syncthreads();
#pragma unroll
    for (int i = 0; i < 4; i++) {
        int d = d0 + ty + i*8;
        h16 val = __float2half_rn(tile[tx][ty + i*8]);
        size_t idx = ((size_t)(b*KVH_ + kvh) * HD_ + d) * L_ + l0 + tx;
        Vt[idx] = val;
    }
}

// ---------------------------------------------------------------------------
// Fused flash attention, single-product fp16 MMA (fp32 accumulate).
// Block: (q-tile 128, head, batch). 256 threads = 8 warps, 16 q-rows each.
// ---------------------------------------------------------------------------
#define QPAD 136
#define VPAD 72

#define QPL  (128*QPAD)
#define KPL  (64*QPAD)
#define VPL  (128*VPAD)
#define QS_OFF 0
#define KS_OFF QPL
#define VS_OFF (KS_OFF + 2*KPL)
#define MS_OFF_H (VS_OFF + 2*VPL)
#define FA_SMEM_BYTES (MS_OFF_H*2 + 2*64*4)

__global__ __launch_bounds__(256, 1)
void k_flash(const h16* __restrict__ qh,
             const h16* __restrict__ kh,
             const h16* __restrict__ vt,
             const int* __restrict__ mask,
             h16* __restrict__ ao)
{
    extern __shared__ h16 sm[];
    h16*   Qs = sm + QS_OFF;
    h16*   Ks = sm + KS_OFF;
    h16*   Vs = sm + VS_OFF;
    float* Ms = (float*)(sm + MS_OFF_H);

    const int tid  = threadIdx.x;
    const int lane = tid & 31;
    const int g    = lane >> 2;
    const int t    = lane & 3;
    const int w    = tid >> 5;

    const int qt = blockIdx.x, h = blockIdx.y, b = blockIdx.z;
    const int kvh = h >> 2;
    const int q0  = qt * 128;

    const h16* Qg = qh + ((size_t)(b*L_ + q0)) * D_ + h * HD_;
    const h16* Kg = kh + ((size_t)(b*L_)) * (KVH_*HD_) + kvh * HD_;
    const h16* Vg = vt + ((size_t)(b*KVH_ + kvh)) * HD_ * L_;

#pragma unroll
    for (int i = 0; i < 8; i++) {
        int c = tid + i * 256;
        int row = c >> 4, ch = c & 15;
        cp16(Qs + row*QPAD + ch*8, Qg + (size_t)row * D_ + ch*8);
    }

    auto load_stage = [&](int s, int kt) {
        const int j0 = kt * 64;
#pragma unroll
        for (int i = 0; i < 4; i++) {
            int c = tid + i * 256;
            int row = c >> 4, ch = c & 15;
            cp16(Ks + s*KPL + row*QPAD + ch*8,
                 Kg + (size_t)(j0 + row) * (KVH_*HD_) + ch*8);
        }
#pragma unroll
        for (int i = 0; i < 4; i++) {
            int c = tid + i * 256;
            int row = c >> 3, ch = c & 7;
            cp16(Vs + s*VPL + row*VPAD + ch*8,
                 Vg + (size_t)row * L_ + j0 + ch*8);
        }
        if (tid < 64)
            Ms[s*64 + tid] = mask[b*L_ + j0 + tid] ? 0.f : -1e30f;
    };

    load_stage(0, 0);
    cp_commit();

    float o[16][4];
#pragma unroll
    for (int i = 0; i < 16; i++)
#pragma unroll
        for (int c = 0; c < 4; c++) o[i][c] = 0.f;

    float mprev0 = -1e30f, mprev1 = -1e30f;
    float lsum0 = 0.f, lsum1 = 0.f;
    const float sc = 0.08838834764831845f;

    const int NT_ = L_ / 64;
    for (int kt = 0; kt < NT_; kt++) {
        const int buf = kt & 1;
        if (kt + 1 < NT_) {
            load_stage(buf ^ 1, kt + 1);
            cp_commit();
            cp_wait<1>();
        } else {
            cp_wait<0>();
        }
        __syncthreads();

        // ---- S = Q K^T : per warp m16 x n64 x k128 ----
        float s[8][4];
#pragma unroll
        for (int nt = 0; nt < 8; nt++)
#pragma unroll
            for (int c = 0; c < 4; c++) s[nt][c] = 0.f;

        const h16* qb = Qs + (w*16 + g)*QPAD + 2*t;
        const h16* kb = Ks + buf*KPL + g*QPAD + 2*t;

#pragma unroll
        for (int kk = 0; kk < 8; kk++) {
            const int ko = kk * 16;
            uint32_t ah[4];
            ah[0] = *(const uint32_t*)(qb + ko);
            ah[1] = *(const uint32_t*)(qb + ko + 8*QPAD);
            ah[2] = *(const uint32_t*)(qb + ko + 8);
            ah[3] = *(const uint32_t*)(qb + ko + 8*QPAD + 8);
#pragma unroll
            for (int nt = 0; nt < 8; nt++) {
                uint32_t bh[2];
                const h16* pk = kb + nt*8*QPAD + ko;
                bh[0] = *(const uint32_t*)(pk);
                bh[1] = *(const uint32_t*)(pk + 8);
                mma_f16(s[nt], ah, bh);
            }
        }

        // ---- online softmax on fragments ----
        const float* msf = Ms + buf*64;
        float m0 = -1e30f, m1 = -1e30f;
#pragma unroll
        for (int nt = 0; nt < 8; nt++) {
            float b0 = msf[8*nt + 2*t], b1 = msf[8*nt + 2*t + 1];
            s[nt][0] = s[nt][0]*sc + b0;
            s[nt][1] = s[nt][1]*sc + b1;
            s[nt][2] = s[nt][2]*sc + b0;
            s[nt][3] = s[nt][3]*sc + b1;
            m0 = fmaxf(m0, fmaxf(s[nt][0], s[nt][1]));
            m1 = fmaxf(m1, fmaxf(s[nt][2], s[nt][3]));
        }
        m0 = fmaxf(m0, __shfl_xor_sync(0xffffffffu, m0, 1));
        m0 = fmaxf(m0, __shfl_xor_sync(0xffffffffu, m0, 2));
        m1 = fmaxf(m1, __shfl_xor_sync(0xffffffffu, m1, 1));
        m1 = fmaxf(m1, __shfl_xor_sync(0xffffffffu, m1, 2));

        const float mn0 = fmaxf(mprev0, m0);
        const float mn1 = fmaxf(mprev1, m1);
        const float alpha0 = __expf(mprev0 - mn0);
        const float alpha1 = __expf(mprev1 - mn1);
        mprev0 = mn0; mprev1 = mn1;

        float sum0 = 0.f, sum1 = 0.f;
#pragma unroll
        for (int nt = 0; nt < 8; nt++) {
            s[nt][0] = __expf(s[nt][0] - mn0);
            s[nt][1] = __expf(s[nt][1] - mn0);
            s[nt][2] = __expf(s[nt][2] - mn1);
            s[nt][3] = __expf(s[nt][3] - mn1);
            sum0 += s[nt][0] + s[nt][1];
            sum1 += s[nt][2] + s[nt][3];
        }
        sum0 += __shfl_xor_sync(0xffffffffu, sum0, 1);
        sum0 += __shfl_xor_sync(0xffffffffu, sum0, 2);
        sum1 += __shfl_xor_sync(0xffffffffu, sum1, 1);
        sum1 += __shfl_xor_sync(0xffffffffu, sum1, 2);
        lsum0 = lsum0 * alpha0 + sum0;
        lsum1 = lsum1 * alpha1 + sum1;

#pragma unroll
        for (int nt = 0; nt < 16; nt++) {
            o[nt][0] *= alpha0; o[nt][1] *= alpha0;
            o[nt][2] *= alpha1; o[nt][3] *= alpha1;
        }

        // ---- P fragments (round to fp16) ----
        uint32_t pah[4][4];
#pragma unroll
        for (int kk = 0; kk < 4; kk++) {
            const int n0t = 2*kk, n1t = 2*kk + 1;
            pah[kk][0] = pack2(__float2half_rn(s[n0t][0]), __float2half_rn(s[n0t][1]));
            pah[kk][1] = pack2(__float2half_rn(s[n0t][2]), __float2half_rn(s[n0t][3]));
            pah[kk][2] = pack2(__float2half_rn(s[n1t][0]), __float2half_rn(s[n1t][1]));
            pah[kk][3] = pack2(__float2half_rn(s[n1t][2]), __float2half_rn(s[n1t][3]));
        }

        // ---- O += P V : per warp m16 x n128 x k64 ----
        const h16* vb = Vs + buf*VPL + g*VPAD + 2*t;
#pragma unroll
        for (int kk = 0; kk < 4; kk++) {
            const int ko = kk * 16;
#pragma unroll
            for (int nt = 0; nt < 16; nt++) {
                uint32_t bh[2];
                const h16* pv = vb + nt*8*VPAD + ko;
                bh[0] = *(const uint32_t*)(pv);
                bh[1] = *(const uint32_t*)(pv + 8);
                mma_f16(o[nt], pah[kk], bh);
            }
        }
        __syncthreads();
    }

    // epilogue: normalize, store fp16
    const float inv0 = lsum0 > 0.f ? 1.f / lsum0 : 0.f;
    const float inv1 = lsum1 > 0.f ? 1.f / lsum1 : 0.f;
    const int row0 = q0 + w*16 + g;
    const size_t base0 = (size_t)(b*L_ + row0) * D_ + h * HD_;
    const size_t base1 = base0 + 8 * (size_t)D_;

#pragma unroll
    for (int nt = 0; nt < 16; nt++) {
        const int col = nt*8 + 2*t;
        *(uint32_t*)(ao + base0 + col) =
            pack2(__float2half_rn(o[nt][0] * inv0), __float2half_rn(o[nt][1] * inv0));
        *(uint32_t*)(ao + base1 + col) =
            pack2(__float2half_rn(o[nt][2] * inv1), __float2half_rn(o[nt][3] * inv1));
    }
}

// ---------------------------------------------------------------------------
// Launch
// ---------------------------------------------------------------------------
extern "C" void kernel_launch(void* const* d_in, const int* in_sizes, int n_in,
                              void* d_out, int out_size) {
    const float* x    = (const float*)d_in[0];
    const int*   mask = (const int*)  d_in[1];
    const float* Wq   = (const float*)d_in[2];
    const float* Wk   = (const float*)d_in[3];
    const float* Wv   = (const float*)d_in[4];
    const float* Wo   = (const float*)d_in[5];
    const float* qg   = (const float*)d_in[6];
    const float* kg   = (const float*)d_in[7];
    float* out = (float*)d_out;

    float *q, *k, *v;
    h16 *xh, *wq, *wk, *wv, *wo;
    h16 *qhp, *khp, *vtp, *aop;
    cudaGetSymbolAddress((void**)&q,   g_q);
    cudaGetSymbolAddress((void**)&k,   g_k);
    cudaGetSymbolAddress((void**)&v,   g_v);
    cudaGetSymbolAddress((void**)&xh,  g_xh);
    cudaGetSymbolAddress((void**)&wq,  g_wq);
    cudaGetSymbolAddress((void**)&wk,  g_wk);
    cudaGetSymbolAddress((void**)&wv,  g_wv);
    cudaGetSymbolAddress((void**)&wo,  g_wo);
    cudaGetSymbolAddress((void**)&qhp, g_qh);
    cudaGetSymbolAddress((void**)&khp, g_kh);
    cudaGetSymbolAddress((void**)&vtp, g_vt);
    cudaGetSymbolAddress((void**)&aop, g_ao);

    cudaFuncSetAttribute(k_gemm_bt1, cudaFuncAttributeMaxDynamicSharedMemorySize, SMEM_TB_BYTES);
    cudaFuncSetAttribute(k_flash,    cudaFuncAttributeMaxDynamicSharedMemorySize, FA_SMEM_BYTES);

    const int M = B_ * L_;
    dim3 blk(256);

    auto launch_cvt = [&](const float* src, h16* hi, int n) {
        int n4 = n / 4;
        k_cvt<<<(n4 + 255) / 256, 256>>>((const float4*)src, (ushort4*)hi, n4);
    };

    // fp16 conversions
    launch_cvt(x,  xh, M * D_);
    launch_cvt(Wq, wq, D_ * D_);
    launch_cvt(Wk, wk, KVH_ * HD_ * D_);
    launch_cvt(Wv, wv, KVH_ * HD_ * D_);
    launch_cvt(Wo, wo, D_ * D_);

    // projections (pure fp16 tensor-core GEMM, fp32 accumulate)
    k_gemm_bt1<<<dim3(D_/BN,         M/BM), blk, SMEM_TB_BYTES>>>(xh, D_, wq, D_, q, D_,       D_);
    k_gemm_bt1<<<dim3((KVH_*HD_)/BN, M/BM), blk, SMEM_TB_BYTES>>>(xh, D_, wk, D_, k, KVH_*HD_, D_);
    k_gemm_bt1<<<dim3((KVH_*HD_)/BN, M/BM), blk, SMEM_TB_BYTES>>>(xh, D_, wv, D_, v, KVH_*HD_, D_);

    // rmsnorm + rope -> fp16 planes
    rms_rope_kernel<<<(B_ * L_ * H_)   / 8, 256>>>(q, qg, qhp, H_);
    rms_rope_kernel<<<(B_ * L_ * KVH_) / 8, 256>>>(k, kg, khp, KVH_);

    // V transpose
    k_vtrans<<<dim3(L_/32, HD_/32, B_*KVH_), 256>>>(v, vtp);

    // fused flash attention -> ao fp16
    k_flash<<<dim3(L_/128, H_, B_), 256, FA_SMEM_BYTES>>>(qhp, khp, vtp, mask, aop);

    // output projection
    k_gemm_bt1<<<dim3(D_/BN, M/BM), blk, SMEM_TB_BYTES>>>(aop, D_, wo, D_, out, D_, D_);
}

// round 9
// speedup vs baseline: 1.6346x; 1.0512x over previous
#include <cuda_runtime.h>
#include <cuda_fp16.h>
#include <math.h>
#include <math_constants.h>
#include <stdint.h>

#define B_    2
#define L_    2048
#define D_    2048
#define H_    16
#define KVH_  4
#define HD_   128
#define KVD_  1024          // packed K|V row width (512 + 512)
#define EPS_  1e-6f

typedef __half h16;

// ---------------------------------------------------------------------------
// Static scratch (all fp16 now)
// ---------------------------------------------------------------------------
__device__ h16 g_x16 [B_*L_*D_];        // x converted
__device__ h16 g_wq16[D_*D_];
__device__ h16 g_wkv [KVD_*D_];         // rows 0-511 = Wk, 512-1023 = Wv
__device__ h16 g_wo16[D_*D_];
__device__ h16 g_q16 [B_*L_*D_];        // q proj (rms+rope in place)
__device__ h16 g_kv  [B_*L_*KVD_];      // packed k|v proj (k rms+roped in place)
__device__ h16 g_vt  [B_*KVH_*HD_*L_];  // V transposed [b][kvh][d][L]
__device__ h16 g_ao  [B_*L_*D_];

// ---------------------------------------------------------------------------
// PTX helpers
// ---------------------------------------------------------------------------
__device__ __forceinline__ void mma_f16(float* c, const uint32_t* a, const uint32_t* b) {
    asm volatile(
        "mma.sync.aligned.m16n8k16.row.col.f32.f16.f16.f32 "
        "{%0,%1,%2,%3}, {%4,%5,%6,%7}, {%8,%9}, {%0,%1,%2,%3};\n"
        : "+f"(c[0]), "+f"(c[1]), "+f"(c[2]), "+f"(c[3])
        : "r"(a[0]), "r"(a[1]), "r"(a[2]), "r"(a[3]), "r"(b[0]), "r"(b[1]));
}

__device__ __forceinline__ void cp16(const h16* dst_s, const h16* src_g) {
    uint32_t d = (uint32_t)__cvta_generic_to_shared(dst_s);
    asm volatile("cp.async.cg.shared.global [%0], [%1], 16;\n"
                 :: "r"(d), "l"(src_g) : "memory");
}
__device__ __forceinline__ void cp_commit() {
    asm volatile("cp.async.commit_group;\n" ::: "memory");
}
template<int N>
__device__ __forceinline__ void cp_wait() {
    asm volatile("cp.async.wait_group %0;\n" :: "n"(N) : "memory");
}

__device__ __forceinline__ uint32_t pack2(h16 a, h16 b) {
    uint32_t x = *reinterpret_cast<unsigned short*>(&a);
    uint32_t y = *reinterpret_cast<unsigned short*>(&b);
    return x | (y << 16);
}

// ---------------------------------------------------------------------------
// GEMM: C[M,N] = A[M,K](h16) * B[N,K]^T(h16), fp32 acc, OutT output.
// 128x128 tile, BK=32, 256 threads, double-buffered cp.async.
// ---------------------------------------------------------------------------
#define BM 128
#define BN 128
#define BK 32
#define APAD 40

#define SM_A_HALVES (2*BM*APAD)
#define SM_B_HALVES (2*BN*APAD)
#define SMEM_TB_BYTES ((SM_A_HALVES + SM_B_HALVES)*2)   // 40960 (< 48KB default)

template<typename OutT>
__global__ __launch_bounds__(256, 1)
void k_gemm(const h16* __restrict__ A, int lda,
            const h16* __restrict__ Bh, int ldb,
            OutT* __restrict__ C, int ldc, int K)
{
    extern __shared__ h16 sh[];
    h16* sA = sh;
    h16* sB = sh + SM_A_HALVES;

    const int tid = threadIdx.x;
    const int m0 = blockIdx.y * BM;
    const int n0 = blockIdx.x * BN;

    const h16* Ap = A  + (size_t)m0 * lda;
    const h16* Bp = Bh + (size_t)n0 * ldb;

    const int lane = tid & 31;
    const int g    = lane >> 2;
    const int t    = lane & 3;
    const int warp = tid >> 5;
    const int wm   = warp >> 2;
    const int wn   = warp & 3;

    float acc[4][4][4];
#pragma unroll
    for (int i = 0; i < 4; i++)
#pragma unroll
        for (int j = 0; j < 4; j++)
#pragma unroll
            for (int c = 0; c < 4; c++) acc[i][j][c] = 0.f;

    auto load_stage = [&](int s, int k0) {
#pragma unroll
        for (int i = 0; i < 2; i++) {
            int c   = tid + i * 256;
            int row = c >> 2, kc = c & 3;
            cp16(sA + (size_t)s*BM*APAD + row*APAD + kc*8,
                 Ap + (size_t)row * lda + k0 + kc*8);
        }
#pragma unroll
        for (int i = 0; i < 2; i++) {
            int c   = tid + i * 256;
            int row = c >> 2, kc = c & 3;
            cp16(sB + (size_t)s*BN*APAD + row*APAD + kc*8,
                 Bp + (size_t)row * ldb + k0 + kc*8);
        }
    };

    const int nk = K / BK;
    load_stage(0, 0);
    cp_commit();

    for (int ks = 0; ks < nk; ks++) {
        const int buf = ks & 1;
        if (ks + 1 < nk) {
            load_stage(buf ^ 1, (ks + 1) * BK);
            cp_commit();
            cp_wait<1>();
        } else {
            cp_wait<0>();
        }
        __syncthreads();

        const h16* sAb = sA + (size_t)buf*BM*APAD;
        const h16* sBb = sB + (size_t)buf*BN*APAD;

#pragma unroll
        for (int kk = 0; kk < 2; kk++) {
            const int ko = kk * 16;

            uint32_t ah[4][4];
#pragma unroll
            for (int mt = 0; mt < 4; mt++) {
                const int r = wm*64 + mt*16 + g;
                const h16* p0 = sAb + r*APAD + ko + 2*t;
                ah[mt][0] = *(const uint32_t*)(p0);
                ah[mt][1] = *(const uint32_t*)(p0 + 8*APAD);
                ah[mt][2] = *(const uint32_t*)(p0 + 8);
                ah[mt][3] = *(const uint32_t*)(p0 + 8*APAD + 8);
            }

            uint32_t bh[4][2];
#pragma unroll
            for (int nt = 0; nt < 4; nt++) {
                const int n = wn*32 + nt*8 + g;
                const h16* p0 = sBb + n*APAD + ko + 2*t;
                bh[nt][0] = *(const uint32_t*)(p0);
                bh[nt][1] = *(const uint32_t*)(p0 + 8);
            }

#pragma unroll
            for (int mt = 0; mt < 4; mt++)
#pragma unroll
                for (int nt = 0; nt < 4; nt++)
                    mma_f16(acc[mt][nt], ah[mt], bh[nt]);
        }
        __syncthreads();
    }

#pragma unroll
    for (int mt = 0; mt < 4; mt++) {
        const int r = m0 + wm*64 + mt*16 + g;
#pragma unroll
        for (int nt = 0; nt < 4; nt++) {
            const int c = n0 + wn*32 + nt*8 + 2*t;
            if constexpr (sizeof(OutT) == 4) {
                *reinterpret_cast<float2*>(&((float*)C)[(size_t)r     * ldc + c]) =
                    make_float2(acc[mt][nt][0], acc[mt][nt][1]);
                *reinterpret_cast<float2*>(&((float*)C)[(size_t)(r+8) * ldc + c]) =
                    make_float2(acc[mt][nt][2], acc[mt][nt][3]);
            } else {
                *(uint32_t*)(&((h16*)C)[(size_t)r     * ldc + c]) =
                    pack2(__float2half_rn(acc[mt][nt][0]), __float2half_rn(acc[mt][nt][1]));
                *(uint32_t*)(&((h16*)C)[(size_t)(r+8) * ldc + c]) =
                    pack2(__float2half_rn(acc[mt][nt][2]), __float2half_rn(acc[mt][nt][3]));
            }
        }
    }
}

// ---------------------------------------------------------------------------
// Fused fp32->fp16 conversion of x + all weights (Wk,Wv packed into g_wkv)
// ---------------------------------------------------------------------------
#define SEG0 2097152u                 // x       (f4 units)
#define SEG1 (SEG0 + 1048576u)        // + Wq
#define SEG2 (SEG1 + 262144u)         // + Wk
#define SEG3 (SEG2 + 262144u)         // + Wv
#define SEG4 (SEG3 + 1048576u)        // + Wo  -> total 4718592

__device__ __forceinline__ ushort4 cvt4(float4 v) {
    h16 a = __float2half_rn(v.x), b = __float2half_rn(v.y);
    h16 c = __float2half_rn(v.z), d = __float2half_rn(v.w);
    ushort4 r;
    r.x = *reinterpret_cast<unsigned short*>(&a);
    r.y = *reinterpret_cast<unsigned short*>(&b);
    r.z = *reinterpret_cast<unsigned short*>(&c);
    r.w = *reinterpret_cast<unsigned short*>(&d);
    return r;
}

__global__ void k_cvt_all(const float4* __restrict__ x,  const float4* __restrict__ wq,
                          const float4* __restrict__ wk, const float4* __restrict__ wv,
                          const float4* __restrict__ wo)
{
    uint32_t i = blockIdx.x * 256u + threadIdx.x;
    ushort4* xh  = (ushort4*)g_x16;
    ushort4* qh  = (ushort4*)g_wq16;
    ushort4* kvh = (ushort4*)g_wkv;
    ushort4* oh  = (ushort4*)g_wo16;
    if (i < SEG0)      xh [i]                     = cvt4(x [i]);
    else if (i < SEG1) qh [i - SEG0]              = cvt4(wq[i - SEG0]);
    else if (i < SEG2) kvh[i - SEG1]              = cvt4(wk[i - SEG1]);
    else if (i < SEG3) kvh[i - SEG2 + 262144u]    = cvt4(wv[i - SEG2]);
    else if (i < SEG4) oh [i - SEG3]              = cvt4(wo[i - SEG3]);
}

// ---------------------------------------------------------------------------
// RMSNorm + RoPE, fp16 in-place. One warp per (b,l,h). rowH = heads per row.
// ---------------------------------------------------------------------------
__global__ void rms_rope_kernel(h16* __restrict__ X,
                                const float* __restrict__ gamma,
                                int heads, int rowH) {
    const int warp = (blockIdx.x * blockDim.x + threadIdx.x) >> 5;
    const int lane = threadIdx.x & 31;
    const int h = warp % heads;
    const int l = (warp / heads) % L_;
    const int b = warp / (heads * L_);

    h16* vec = X + ((size_t)(b * L_ + l) * rowH + h) * HD_;

    const int p0 = lane, p1 = lane + 32;
    float x0a = __half2float(vec[2*p0]),   x1a = __half2float(vec[2*p0+1]);
    float x0b = __half2float(vec[2*p1]),   x1b = __half2float(vec[2*p1+1]);

    float ss = x0a*x0a + x1a*x1a + x0b*x0b + x1b*x1b;
#pragma unroll
    for (int off = 16; off; off >>= 1)
        ss += __shfl_xor_sync(0xffffffffu, ss, off);

    const float inv = rsqrtf(ss * (1.0f / HD_) + EPS_);
    const float LOG2_THETA = 13.287712379549449f;
    const float fl = (float)l;

    {
        float g0 = gamma[2*p0], g1 = gamma[2*p0+1];
        float re = x0a * inv * g0, im = x1a * inv * g1;
        float fr = fl * exp2f(-(2.0f * p0 / (float)HD_) * LOG2_THETA);
        float s, c; sincosf(fr, &s, &c);
        vec[2*p0]   = __float2half_rn(re * c - im * s);
        vec[2*p0+1] = __float2half_rn(re * s + im * c);
    }
    {
        float g0 = gamma[2*p1], g1 = gamma[2*p1+1];
        float re = x0b * inv * g0, im = x1b * inv * g1;
        float fr = fl * exp2f(-(2.0f * p1 / (float)HD_) * LOG2_THETA);
        float s, c; sincosf(fr, &s, &c);
        vec[2*p1]   = __float2half_rn(re * c - im * s);
        vec[2*p1+1] = __float2half_rn(re * s + im * c);
    }
}

// ---------------------------------------------------------------------------
// V transpose: kv fp16 [b][l][1024] (v at +512) -> vt [b][kvh][d][L]
// ---------------------------------------------------------------------------
__global__ void k_vtrans(const h16* __restrict__ KV, h16* __restrict__ Vt)
{
    __shared__ h16 tile[32][34];
    const int tx = threadIdx.x & 31;
    const int ty = threadIdx.x >> 5;
    const int l0 = blockIdx.x * 32;
    const int d0 = blockIdx.y * 32;
    const int z  = blockIdx.z;
    const int b  = z >> 2, kvh = z & 3;

#pragma unroll
    for (int i = 0; i < 4; i++) {
        int l = l0 + ty + i*8;
        tile[ty + i*8][tx] =
            KV[(size_t)(b*L_ + l) * KVD_ + 512 + kvh * HD_ + d0 + tx];
    }
    __syncthreads();
#pragma unroll
    for (int i = 0; i < 4; i++) {
        int d = d0 + ty + i*8;
        size_t idx = ((size_t)(b*KVH_ + kvh) * HD_ + d) * L_ + l0 + tx;
        Vt[idx] = tile[tx][ty + i*8];
    }
}

// ---------------------------------------------------------------------------
// Fused flash attention, fixed-shift softmax (no online max — scores provably
// bounded |s|<=11.3 after rmsnorm; exp(s-6) <= e^5.3 fits fp16 easily).
// Block: (q-tile 128, head, batch). 256 threads = 8 warps, 16 q-rows each.
// ---------------------------------------------------------------------------
#define QPAD 136
#define VPAD 72

#define QPL  (128*QPAD)
#define KPL  (64*QPAD)
#define VPL  (128*VPAD)
#define QS_OFF 0
#define KS_OFF QPL
#define VS_OFF (KS_OFF + 2*KPL)
#define MS_OFF_H (VS_OFF + 2*VPL)
#define FA_SMEM_BYTES (MS_OFF_H*2 + 2*64*4)

__global__ __launch_bounds__(256, 1)
void k_flash(const h16* __restrict__ qh,
             const h16* __restrict__ kv,
             const h16* __restrict__ vt,
             const int* __restrict__ mask,
             h16* __restrict__ ao)
{
    extern __shared__ h16 sm[];
    h16*   Qs = sm + QS_OFF;
    h16*   Ks = sm + KS_OFF;
    h16*   Vs = sm + VS_OFF;
    float* Ms = (float*)(sm + MS_OFF_H);

    const int tid  = threadIdx.x;
    const int lane = tid & 31;
    const int g    = lane >> 2;
    const int t    = lane & 3;
    const int w    = tid >> 5;

    const int qt = blockIdx.x, h = blockIdx.y, b = blockIdx.z;
    const int kvh = h >> 2;
    const int q0  = qt * 128;

    const h16* Qg = qh + ((size_t)(b*L_ + q0)) * D_ + h * HD_;
    const h16* Kg = kv + ((size_t)(b*L_)) * KVD_ + kvh * HD_;
    const h16* Vg = vt + ((size_t)(b*KVH_ + kvh)) * HD_ * L_;

#pragma unroll
    for (int i = 0; i < 8; i++) {
        int c = tid + i * 256;
        int row = c >> 4, ch = c & 15;
        cp16(Qs + row*QPAD + ch*8, Qg + (size_t)row * D_ + ch*8);
    }

    auto load_stage = [&](int s, int kt) {
        const int j0 = kt * 64;
#pragma unroll
        for (int i = 0; i < 4; i++) {
            int c = tid + i * 256;
            int row = c >> 4, ch = c & 15;
            cp16(Ks + s*KPL + row*QPAD + ch*8,
                 Kg + (size_t)(j0 + row) * KVD_ + ch*8);
        }
#pragma unroll
        for (int i = 0; i < 4; i++) {
            int c = tid + i * 256;
            int row = c >> 3, ch = c & 7;
            cp16(Vs + s*VPL + row*VPAD + ch*8,
                 Vg + (size_t)row * L_ + j0 + ch*8);
        }
        if (tid < 64)
            Ms[s*64 + tid] = mask[b*L_ + j0 + tid] ? -6.0f : -1e30f;  // shift folded in
    };

    load_stage(0, 0);
    cp_commit();

    float o[16][4];
#pragma unroll
    for (int i = 0; i < 16; i++)
#pragma unroll
        for (int c = 0; c < 4; c++) o[i][c] = 0.f;

    float lsum0 = 0.f, lsum1 = 0.f;   // per-thread partials; reduced at end
    const float sc = 0.08838834764831845f;

    const int NT_ = L_ / 64;
    for (int kt = 0; kt < NT_; kt++) {
        const int buf = kt & 1;
        if (kt + 1 < NT_) {
            load_stage(buf ^ 1, kt + 1);
            cp_commit();
            cp_wait<1>();
        } else {
            cp_wait<0>();
        }
        __syncthreads();

        // ---- S = Q K^T : per warp m16 x n64 x k128 ----
        float s[8][4];
#pragma unroll
        for (int nt = 0; nt < 8; nt++)
#pragma unroll
            for (int c = 0; c < 4; c++) s[nt][c] = 0.f;

        const h16* qb = Qs + (w*16 + g)*QPAD + 2*t;
        const h16* kb = Ks + buf*KPL + g*QPAD + 2*t;

#pragma unroll
        for (int kk = 0; kk < 8; kk++) {
            const int ko = kk * 16;
            uint32_t ah[4];
            ah[0] = *(const uint32_t*)(qb + ko);
            ah[1] = *(const uint32_t*)(qb + ko + 8*QPAD);
            ah[2] = *(const uint32_t*)(qb + ko + 8);
            ah[3] = *(const uint32_t*)(qb + ko + 8*QPAD + 8);
#pragma unroll
            for (int nt = 0; nt < 8; nt++) {
                uint32_t bh[2];
                const h16* pk = kb + nt*8*QPAD + ko;
                bh[0] = *(const uint32_t*)(pk);
                bh[1] = *(const uint32_t*)(pk + 8);
                mma_f16(s[nt], ah, bh);
            }
        }

        // ---- fixed-shift exp + sum + fp16 P fragments ----
        const float* msf = Ms + buf*64;
        uint32_t pah[4][4];
#pragma unroll
        for (int kk = 0; kk < 4; kk++) {
            const int n0t = 2*kk, n1t = 2*kk + 1;
            float b00 = msf[8*n0t + 2*t], b01 = msf[8*n0t + 2*t + 1];
            float b10 = msf[8*n1t + 2*t], b11 = msf[8*n1t + 2*t + 1];
            float p00 = __expf(s[n0t][0]*sc + b00);
            float p01 = __expf(s[n0t][1]*sc + b01);
            float p02 = __expf(s[n0t][2]*sc + b00);
            float p03 = __expf(s[n0t][3]*sc + b01);
            float p10 = __expf(s[n1t][0]*sc + b10);
            float p11 = __expf(s[n1t][1]*sc + b11);
            float p12 = __expf(s[n1t][2]*sc + b10);
            float p13 = __expf(s[n1t][3]*sc + b11);
            lsum0 += p00 + p01 + p10 + p11;
            lsum1 += p02 + p03 + p12 + p13;
            pah[kk][0] = pack2(__float2half_rn(p00), __float2half_rn(p01));
            pah[kk][1] = pack2(__float2half_rn(p02), __float2half_rn(p03));
            pah[kk][2] = pack2(__float2half_rn(p10), __float2half_rn(p11));
            pah[kk][3] = pack2(__float2half_rn(p12), __float2half_rn(p13));
        }

        // ---- O += P V : per warp m16 x n128 x k64 ----
        const h16* vb = Vs + buf*VPL + g*VPAD + 2*t;
#pragma unroll
        for (int kk = 0; kk < 4; kk++) {
            const int ko = kk * 16;
#pragma unroll
            for (int nt = 0; nt < 16; nt++) {
                uint32_t bh[2];
                const h16* pv = vb + nt*8*VPAD + ko;
                bh[0] = *(const uint32_t*)(pv);
                bh[1] = *(const uint32_t*)(pv + 8);
                mma_f16(o[nt], pah[kk], bh);
            }
        }
        __syncthreads();
    }

    // row-sum reduce across the 4-lane quad (once, at the end)
    lsum0 += __shfl_xor_sync(0xffffffffu, lsum0, 1);
    lsum0 += __shfl_xor_sync(0xffffffffu, lsum0, 2);
    lsum1 += __shfl_xor_sync(0xffffffffu, lsum1, 1);
    lsum1 += __shfl_xor_sync(0xffffffffu, lsum1, 2);

    const float inv0 = lsum0 > 0.f ? 1.f / lsum0 : 0.f;
    const float inv1 = lsum1 > 0.f ? 1.f / lsum1 : 0.f;
    const int row0 = q0 + w*16 + g;
    const size_t base0 = (size_t)(b*L_ + row0) * D_ + h * HD_;
    const size_t base1 = base0 + 8 * (size_t)D_;

#pragma unroll
    for (int nt = 0; nt < 16; nt++) {
        const int col = nt*8 + 2*t;
        *(uint32_t*)(ao + base0 + col) =
            pack2(__float2half_rn(o[nt][0] * inv0), __float2half_rn(o[nt][1] * inv0));
        *(uint32_t*)(ao + base1 + col) =
            pack2(__float2half_rn(o[nt][2] * inv1), __float2half_rn(o[nt][3] * inv1));
    }
}

// ---------------------------------------------------------------------------
// Launch
// ---------------------------------------------------------------------------
extern "C" void kernel_launch(void* const* d_in, const int* in_sizes, int n_in,
                              void* d_out, int out_size) {
    const float* x    = (const float*)d_in[0];
    const int*   mask = (const int*)  d_in[1];
    const float* Wq   = (const float*)d_in[2];
    const float* Wk   = (const float*)d_in[3];
    const float* Wv   = (const float*)d_in[4];
    const float* Wo   = (const float*)d_in[5];
    const float* qg   = (const float*)d_in[6];
    const float* kg   = (const float*)d_in[7];
    float* out = (float*)d_out;

    h16 *x16, *wq16, *wkv, *wo16, *q16, *kvp, *vtp, *aop;
    cudaGetSymbolAddress((void**)&x16,  g_x16);
    cudaGetSymbolAddress((void**)&wq16, g_wq16);
    cudaGetSymbolAddress((void**)&wkv,  g_wkv);
    cudaGetSymbolAddress((void**)&wo16, g_wo16);
    cudaGetSymbolAddress((void**)&q16,  g_q16);
    cudaGetSymbolAddress((void**)&kvp,  g_kv);
    cudaGetSymbolAddress((void**)&vtp,  g_vt);
    cudaGetSymbolAddress((void**)&aop,  g_ao);

    cudaFuncSetAttribute(k_flash, cudaFuncAttributeMaxDynamicSharedMemorySize,
                         FA_SMEM_BYTES);

    const int M = B_ * L_;
    dim3 blk(256);

    // fused fp32->fp16 conversion (x, Wq, Wk|Wv packed, Wo)
    k_cvt_all<<<SEG4 / 256, 256>>>((const float4*)x,  (const float4*)Wq,
                                   (const float4*)Wk, (const float4*)Wv,
                                   (const float4*)Wo);

    // projections: Q (N=2048) and fused K|V (N=1024), fp16 out
    k_gemm<h16><<<dim3(D_/BN,   M/BM), blk, SMEM_TB_BYTES>>>(x16, D_, wq16, D_, q16, D_,   D_);
    k_gemm<h16><<<dim3(KVD_/BN, M/BM), blk, SMEM_TB_BYTES>>>(x16, D_, wkv,  D_, kvp, KVD_, D_);

    // rmsnorm + rope in place (q: 16 heads/row of 16; k: 4 heads/row of 8)
    rms_rope_kernel<<<(B_ * L_ * H_)   / 8, 256>>>(q16, qg, H_,   H_);
    rms_rope_kernel<<<(B_ * L_ * KVH_) / 8, 256>>>(kvp, kg, KVH_, KVD_/HD_);

    // V transpose out of packed kv
    k_vtrans<<<dim3(L_/32, HD_/32, B_*KVH_), 256>>>(kvp, vtp);

    // fused flash attention -> ao fp16
    k_flash<<<dim3(L_/128, H_, B_), 256, FA_SMEM_BYTES>>>(q16, kvp, vtp, mask, aop);

    // output projection -> fp32 out
    k_gemm<float><<<dim3(D_/BN, M/BM), blk, SMEM_TB_BYTES>>>(aop, D_, wo16, D_, out, D_, D_);
}

// round 10
// speedup vs baseline: 1.8419x; 1.1268x over previous
#include <cuda_runtime.h>
#include <cuda_fp16.h>
#include <math.h>
#include <math_constants.h>
#include <stdint.h>

#define B_    2
#define L_    2048
#define D_    2048
#define H_    16
#define KVH_  4
#define HD_   128
#define KVD_  1024
#define EPS_  1e-6f

typedef __half h16;

// ---------------------------------------------------------------------------
// Static scratch (all fp16)
// ---------------------------------------------------------------------------
__device__ h16 g_x16 [B_*L_*D_];
__device__ h16 g_wq16[D_*D_];
__device__ h16 g_wkv [KVD_*D_];         // rows 0-511 = Wk, 512-1023 = Wv
__device__ h16 g_wo16[D_*D_];
__device__ h16 g_q16 [B_*L_*D_];        // q proj, rms+rope applied in epilogue
__device__ h16 g_kv  [B_*L_*KVD_];      // packed k|v proj (k rms+roped in epilogue)
__device__ h16 g_vt  [B_*KVH_*HD_*L_];
__device__ h16 g_ao  [B_*L_*D_];

// ---------------------------------------------------------------------------
// PTX helpers
// ---------------------------------------------------------------------------
__device__ __forceinline__ void mma_f16(float* c, const uint32_t* a, const uint32_t* b) {
    asm volatile(
        "mma.sync.aligned.m16n8k16.row.col.f32.f16.f16.f32 "
        "{%0,%1,%2,%3}, {%4,%5,%6,%7}, {%8,%9}, {%0,%1,%2,%3};\n"
        : "+f"(c[0]), "+f"(c[1]), "+f"(c[2]), "+f"(c[3])
        : "r"(a[0]), "r"(a[1]), "r"(a[2]), "r"(a[3]), "r"(b[0]), "r"(b[1]));
}

__device__ __forceinline__ void cp16(const h16* dst_s, const h16* src_g) {
    uint32_t d = (uint32_t)__cvta_generic_to_shared(dst_s);
    asm volatile("cp.async.cg.shared.global [%0], [%1], 16;\n"
                 :: "r"(d), "l"(src_g) : "memory");
}
__device__ __forceinline__ void cp_commit() {
    asm volatile("cp.async.commit_group;\n" ::: "memory");
}
template<int N>
__device__ __forceinline__ void cp_wait() {
    asm volatile("cp.async.wait_group %0;\n" :: "n"(N) : "memory");
}

__device__ __forceinline__ uint32_t pack2(h16 a, h16 b) {
    uint32_t x = *reinterpret_cast<unsigned short*>(&a);
    uint32_t y = *reinterpret_cast<unsigned short*>(&b);
    return x | (y << 16);
}

// ---------------------------------------------------------------------------
// GEMM: C[M,N] = A[M,K](h16) * B[N,K]^T(h16), fp32 acc.
// MODE 0: fp32 out. MODE 1: fp16 out + rmsnorm+rope (all blocks = Q proj).
// MODE 2: fp16 out; rmsnorm+rope only for n0<512 (K half of KV proj).
// 128x128 tile, BK=32, 256 threads, double-buffered cp.async, 2 CTAs/SM.
// ---------------------------------------------------------------------------
#define BM 128
#define BN 128
#define BK 32
#define APAD 40

#define SM_A_HALVES (2*BM*APAD)
#define SM_B_HALVES (2*BN*APAD)
#define SMEM_TB_BYTES ((SM_A_HALVES + SM_B_HALVES)*2)   // 40960

#define INVF_C 0.2076205059304601f    // log2(10000)/64

template<int MODE>
__global__ __launch_bounds__(256, 2)
void k_gemm(const h16* __restrict__ A, int lda,
            const h16* __restrict__ Bh, int ldb,
            void* __restrict__ Cv, int ldc, int K,
            const float* __restrict__ gamma)
{
    extern __shared__ h16 sh[];
    h16* sA = sh;
    h16* sB = sh + SM_A_HALVES;

    const int tid = threadIdx.x;
    const int m0 = blockIdx.y * BM;
    const int n0 = blockIdx.x * BN;

    const h16* Ap = A  + (size_t)m0 * lda;
    const h16* Bp = Bh + (size_t)n0 * ldb;

    const int lane = tid & 31;
    const int g    = lane >> 2;
    const int t    = lane & 3;
    const int warp = tid >> 5;
    const int wm   = warp >> 2;
    const int wn   = warp & 3;

    float acc[4][4][4];
#pragma unroll
    for (int i = 0; i < 4; i++)
#pragma unroll
        for (int j = 0; j < 4; j++)
#pragma unroll
            for (int c = 0; c < 4; c++) acc[i][j][c] = 0.f;

    auto load_stage = [&](int s, int k0) {
#pragma unroll
        for (int i = 0; i < 2; i++) {
            int c   = tid + i * 256;
            int row = c >> 2, kc = c & 3;
            cp16(sA + (size_t)s*BM*APAD + row*APAD + kc*8,
                 Ap + (size_t)row * lda + k0 + kc*8);
        }
#pragma unroll
        for (int i = 0; i < 2; i++) {
            int c   = tid + i * 256;
            int row = c >> 2, kc = c & 3;
            cp16(sB + (size_t)s*BN*APAD + row*APAD + kc*8,
                 Bp + (size_t)row * ldb + k0 + kc*8);
        }
    };

    const int nk = K / BK;
    load_stage(0, 0);
    cp_commit();

    for (int ks = 0; ks < nk; ks++) {
        const int buf = ks & 1;
        if (ks + 1 < nk) {
            load_stage(buf ^ 1, (ks + 1) * BK);
            cp_commit();
            cp_wait<1>();
        } else {
            cp_wait<0>();
        }
        __syncthreads();

        const h16* sAb = sA + (size_t)buf*BM*APAD;
        const h16* sBb = sB + (size_t)buf*BN*APAD;

#pragma unroll
        for (int kk = 0; kk < 2; kk++) {
            const int ko = kk * 16;

            uint32_t ah[4][4];
#pragma unroll
            for (int mt = 0; mt < 4; mt++) {
                const int r = wm*64 + mt*16 + g;
                const h16* p0 = sAb + r*APAD + ko + 2*t;
                ah[mt][0] = *(const uint32_t*)(p0);
                ah[mt][1] = *(const uint32_t*)(p0 + 8*APAD);
                ah[mt][2] = *(const uint32_t*)(p0 + 8);
                ah[mt][3] = *(const uint32_t*)(p0 + 8*APAD + 8);
            }

            uint32_t bh[4][2];
#pragma unroll
            for (int nt = 0; nt < 4; nt++) {
                const int n = wn*32 + nt*8 + g;
                const h16* p0 = sBb + n*APAD + ko + 2*t;
                bh[nt][0] = *(const uint32_t*)(p0);
                bh[nt][1] = *(const uint32_t*)(p0 + 8);
            }

#pragma unroll
            for (int mt = 0; mt < 4; mt++)
#pragma unroll
                for (int nt = 0; nt < 4; nt++)
                    mma_f16(acc[mt][nt], ah[mt], bh[nt]);
        }
        __syncthreads();
    }

    // ---------------- epilogue ----------------
    if constexpr (MODE == 0) {
        float* C = (float*)Cv;
#pragma unroll
        for (int mt = 0; mt < 4; mt++) {
            const int r = m0 + wm*64 + mt*16 + g;
#pragma unroll
            for (int nt = 0; nt < 4; nt++) {
                const int c = n0 + wn*32 + nt*8 + 2*t;
                *reinterpret_cast<float2*>(&C[(size_t)r     * ldc + c]) =
                    make_float2(acc[mt][nt][0], acc[mt][nt][1]);
                *reinterpret_cast<float2*>(&C[(size_t)(r+8) * ldc + c]) =
                    make_float2(acc[mt][nt][2], acc[mt][nt][3]);
            }
        }
    } else {
        h16* C = (h16*)Cv;
        const bool dorms = (MODE == 1) || (n0 < 512);
        if (!dorms) {
            // plain fp16 store (V half of KV projection)
#pragma unroll
            for (int mt = 0; mt < 4; mt++) {
                const int r = m0 + wm*64 + mt*16 + g;
#pragma unroll
                for (int nt = 0; nt < 4; nt++) {
                    const int c = n0 + wn*32 + nt*8 + 2*t;
                    *(uint32_t*)(&C[(size_t)r     * ldc + c]) =
                        pack2(__float2half_rn(acc[mt][nt][0]), __float2half_rn(acc[mt][nt][1]));
                    *(uint32_t*)(&C[(size_t)(r+8) * ldc + c]) =
                        pack2(__float2half_rn(acc[mt][nt][2]), __float2half_rn(acc[mt][nt][3]));
                }
            }
        } else {
            // fused rmsnorm + rope: block covers exactly one head (128 dims)
            float* red = (float*)sh;   // smem free after last barrier; need 512 floats
            float part[4][2];
#pragma unroll
            for (int mt = 0; mt < 4; mt++)
#pragma unroll
                for (int hh = 0; hh < 2; hh++) {
                    float p = 0.f;
#pragma unroll
                    for (int nt = 0; nt < 4; nt++) {
                        float a0 = acc[mt][nt][2*hh], a1 = acc[mt][nt][2*hh+1];
                        p += a0*a0 + a1*a1;
                    }
                    p += __shfl_xor_sync(0xffffffffu, p, 1);
                    p += __shfl_xor_sync(0xffffffffu, p, 2);
                    part[mt][hh] = p;
                }
            if (t == 0) {
#pragma unroll
                for (int mt = 0; mt < 4; mt++)
#pragma unroll
                    for (int hh = 0; hh < 2; hh++)
                        red[(wm*64 + mt*16 + g + hh*8)*4 + wn] = part[mt][hh];
            }
            __syncthreads();

            float invv[4][2];
#pragma unroll
            for (int mt = 0; mt < 4; mt++)
#pragma unroll
                for (int hh = 0; hh < 2; hh++) {
                    int rl = wm*64 + mt*16 + g + hh*8;
                    float s = red[rl*4] + red[rl*4+1] + red[rl*4+2] + red[rl*4+3];
                    invv[mt][hh] = rsqrtf(s * (1.0f/HD_) + EPS_);
                }

            float invf[4], g0[4], g1[4];
#pragma unroll
            for (int nt = 0; nt < 4; nt++) {
                int p = wn*16 + nt*4 + t;
                invf[nt] = exp2f(-(float)p * INVF_C);
                g0[nt] = gamma[2*p];
                g1[nt] = gamma[2*p+1];
            }

#pragma unroll
            for (int mt = 0; mt < 4; mt++)
#pragma unroll
                for (int hh = 0; hh < 2; hh++) {
                    const int r  = m0 + wm*64 + mt*16 + g + hh*8;
                    const float fl = (float)(r & (L_-1));
                    const float iv = invv[mt][hh];
#pragma unroll
                    for (int nt = 0; nt < 4; nt++) {
                        float sn, cs;
                        sincosf(fl * invf[nt], &sn, &cs);
                        float re = acc[mt][nt][2*hh]   * iv * g0[nt];
                        float im = acc[mt][nt][2*hh+1] * iv * g1[nt];
                        h16* dst = C + (size_t)r * ldc + n0 + wn*32 + nt*8 + 2*t;
                        *(uint32_t*)dst = pack2(__float2half_rn(re*cs - im*sn),
                                                __float2half_rn(re*sn + im*cs));
                    }
                }
        }
    }
}

// ---------------------------------------------------------------------------
// fp32->fp16 conversion: main (x, Wq, Wk|Wv packed) and Wo (separate stream)
// ---------------------------------------------------------------------------
#define CS0 2097152u                 // x       (f4 units)
#define CS1 (CS0 + 1048576u)         // + Wq
#define CS2 (CS1 + 262144u)          // + Wk
#define CS3 (CS2 + 262144u)          // + Wv -> 3670016 total

__device__ __forceinline__ ushort4 cvt4(float4 v) {
    h16 a = __float2half_rn(v.x), b = __float2half_rn(v.y);
    h16 c = __float2half_rn(v.z), d = __float2half_rn(v.w);
    ushort4 r;
    r.x = *reinterpret_cast<unsigned short*>(&a);
    r.y = *reinterpret_cast<unsigned short*>(&b);
    r.z = *reinterpret_cast<unsigned short*>(&c);
    r.w = *reinterpret_cast<unsigned short*>(&d);
    return r;
}

__global__ void k_cvt_main(const float4* __restrict__ x, const float4* __restrict__ wq,
                           const float4* __restrict__ wk, const float4* __restrict__ wv)
{
    uint32_t i = blockIdx.x * 256u + threadIdx.x;
    ushort4* xh  = (ushort4*)g_x16;
    ushort4* qh  = (ushort4*)g_wq16;
    ushort4* kvh = (ushort4*)g_wkv;
    if (i < CS0)      xh [i]                  = cvt4(x [i]);
    else if (i < CS1) qh [i - CS0]            = cvt4(wq[i - CS0]);
    else if (i < CS2) kvh[i - CS1]            = cvt4(wk[i - CS1]);
    else if (i < CS3) kvh[i - CS2 + 262144u]  = cvt4(wv[i - CS2]);
}

__global__ void k_cvt_wo(const float4* __restrict__ wo)
{
    uint32_t i = blockIdx.x * 256u + threadIdx.x;
    ((ushort4*)g_wo16)[i] = cvt4(wo[i]);
}

// ---------------------------------------------------------------------------
// V transpose: kv fp16 [b][l][1024] (v at +512) -> vt [b][kvh][d][L]
// ---------------------------------------------------------------------------
__global__ void k_vtrans(const h16* __restrict__ KV, h16* __restrict__ Vt)
{
    __shared__ h16 tile[32][34];
    const int tx = threadIdx.x & 31;
    const int ty = threadIdx.x >> 5;
    const int l0 = blockIdx.x * 32;
    const int d0 = blockIdx.y * 32;
    const int z  = blockIdx.z;
    const int b  = z >> 2, kvh = z & 3;

#pragma unroll
    for (int i = 0; i < 4; i++) {
        int l = l0 + ty + i*8;
        tile[ty + i*8][tx] =
            KV[(size_t)(b*L_ + l) * KVD_ + 512 + kvh * HD_ + d0 + tx];
    }
    __syncthreads();
#pragma unroll
    for (int i = 0; i < 4; i++) {
        int d = d0 + ty + i*8;
        size_t idx = ((size_t)(b*KVH_ + kvh) * HD_ + d) * L_ + l0 + tx;
        Vt[idx] = tile[tx][ty + i*8];
    }
}

// ---------------------------------------------------------------------------
// Fused flash attention, fixed-shift softmax (scores bounded post-rmsnorm).
// ---------------------------------------------------------------------------
#define QPAD 136
#define VPAD 72

#define QPL  (128*QPAD)
#define KPL  (64*QPAD)
#define VPL  (128*VPAD)
#define QS_OFF 0
#define KS_OFF QPL
#define VS_OFF (KS_OFF + 2*KPL)
#define MS_OFF_H (VS_OFF + 2*VPL)
#define FA_SMEM_BYTES (MS_OFF_H*2 + 2*64*4)

__global__ __launch_bounds__(256, 1)
void k_flash(const h16* __restrict__ qh,
             const h16* __restrict__ kv,
             const h16* __restrict__ vt,
             const int* __restrict__ mask,
             h16* __restrict__ ao)
{
    extern __shared__ h16 sm[];
    h16*   Qs = sm + QS_OFF;
    h16*   Ks = sm + KS_OFF;
    h16*   Vs = sm + VS_OFF;
    float* Ms = (float*)(sm + MS_OFF_H);

    const int tid  = threadIdx.x;
    const int lane = tid & 31;
    const int g    = lane >> 2;
    const int t    = lane & 3;
    const int w    = tid >> 5;

    const int qt = blockIdx.x, h = blockIdx.y, b = blockIdx.z;
    const int kvh = h >> 2;
    const int q0  = qt * 128;

    const h16* Qg = qh + ((size_t)(b*L_ + q0)) * D_ + h * HD_;
    const h16* Kg = kv + ((size_t)(b*L_)) * KVD_ + kvh * HD_;
    const h16* Vg = vt + ((size_t)(b*KVH_ + kvh)) * HD_ * L_;

#pragma unroll
    for (int i = 0; i < 8; i++) {
        int c = tid + i * 256;
        int row = c >> 4, ch = c & 15;
        cp16(Qs + row*QPAD + ch*8, Qg + (size_t)row * D_ + ch*8);
    }

    auto load_stage = [&](int s, int kt) {
        const int j0 = kt * 64;
#pragma unroll
        for (int i = 0; i < 4; i++) {
            int c = tid + i * 256;
            int row = c >> 4, ch = c & 15;
            cp16(Ks + s*KPL + row*QPAD + ch*8,
                 Kg + (size_t)(j0 + row) * KVD_ + ch*8);
        }
#pragma unroll
        for (int i = 0; i < 4; i++) {
            int c = tid + i * 256;
            int row = c >> 3, ch = c & 7;
            cp16(Vs + s*VPL + row*VPAD + ch*8,
                 Vg + (size_t)row * L_ + j0 + ch*8);
        }
        if (tid < 64)
            Ms[s*64 + tid] = mask[b*L_ + j0 + tid] ? -6.0f : -1e30f;
    };

    load_stage(0, 0);
    cp_commit();

    float o[16][4];
#pragma unroll
    for (int i = 0; i < 16; i++)
#pragma unroll
        for (int c = 0; c < 4; c++) o[i][c] = 0.f;

    float lsum0 = 0.f, lsum1 = 0.f;
    const float sc = 0.08838834764831845f;

    const int NT_ = L_ / 64;
    for (int kt = 0; kt < NT_; kt++) {
        const int buf = kt & 1;
        if (kt + 1 < NT_) {
            load_stage(buf ^ 1, kt + 1);
            cp_commit();
            cp_wait<1>();
        } else {
            cp_wait<0>();
        }
        __syncthreads();

        float s[8][4];
#pragma unroll
        for (int nt = 0; nt < 8; nt++)
#pragma unroll
            for (int c = 0; c < 4; c++) s[nt][c] = 0.f;

        const h16* qb = Qs + (w*16 + g)*QPAD + 2*t;
        const h16* kb = Ks + buf*KPL + g*QPAD + 2*t;

#pragma unroll
        for (int kk = 0; kk < 8; kk++) {
            const int ko = kk * 16;
            uint32_t ah[4];
            ah[0] = *(const uint32_t*)(qb + ko);
            ah[1] = *(const uint32_t*)(qb + ko + 8*QPAD);
            ah[2] = *(const uint32_t*)(qb + ko + 8);
            ah[3] = *(const uint32_t*)(qb + ko + 8*QPAD + 8);
#pragma unroll
            for (int nt = 0; nt < 8; nt++) {
                uint32_t bh[2];
                const h16* pk = kb + nt*8*QPAD + ko;
                bh[0] = *(const uint32_t*)(pk);
                bh[1] = *(const uint32_t*)(pk + 8);
                mma_f16(s[nt], ah, bh);
            }
        }

        const float* msf = Ms + buf*64;
        uint32_t pah[4][4];
#pragma unroll
        for (int kk = 0; kk < 4; kk++) {
            const int n0t = 2*kk, n1t = 2*kk + 1;
            float b00 = msf[8*n0t + 2*t], b01 = msf[8*n0t + 2*t + 1];
            float b10 = msf[8*n1t + 2*t], b11 = msf[8*n1t + 2*t + 1];
            float p00 = __expf(s[n0t][0]*sc + b00);
            float p01 = __expf(s[n0t][1]*sc + b01);
            float p02 = __expf(s[n0t][2]*sc + b00);
            float p03 = __expf(s[n0t][3]*sc + b01);
            float p10 = __expf(s[n1t][0]*sc + b10);
            float p11 = __expf(s[n1t][1]*sc + b11);
            float p12 = __expf(s[n1t][2]*sc + b10);
            float p13 = __expf(s[n1t][3]*sc + b11);
            lsum0 += p00 + p01 + p10 + p11;
            lsum1 += p02 + p03 + p12 + p13;
            pah[kk][0] = pack2(__float2half_rn(p00), __float2half_rn(p01));
            pah[kk][1] = pack2(__float2half_rn(p02), __float2half_rn(p03));
            pah[kk][2] = pack2(__float2half_rn(p10), __float2half_rn(p11));
            pah[kk][3] = pack2(__float2half_rn(p12), __float2half_rn(p13));
        }

        const h16* vb = Vs + buf*VPL + g*VPAD + 2*t;
#pragma unroll
        for (int kk = 0; kk < 4; kk++) {
            const int ko = kk * 16;
#pragma unroll
            for (int nt = 0; nt < 16; nt++) {
                uint32_t bh[2];
                const h16* pv = vb + nt*8*VPAD + ko;
                bh[0] = *(const uint32_t*)(pv);
                bh[1] = *(const uint32_t*)(pv + 8);
                mma_f16(o[nt], pah[kk], bh);
            }
        }
        __syncthreads();
    }

    lsum0 += __shfl_xor_sync(0xffffffffu, lsum0, 1);
    lsum0 += __shfl_xor_sync(0xffffffffu, lsum0, 2);
    lsum1 += __shfl_xor_sync(0xffffffffu, lsum1, 1);
    lsum1 += __shfl_xor_sync(0xffffffffu, lsum1, 2);

    const float inv0 = lsum0 > 0.f ? 1.f / lsum0 : 0.f;
    const float inv1 = lsum1 > 0.f ? 1.f / lsum1 : 0.f;
    const int row0 = q0 + w*16 + g;
    const size_t base0 = (size_t)(b*L_ + row0) * D_ + h * HD_;
    const size_t base1 = base0 + 8 * (size_t)D_;

#pragma unroll
    for (int nt = 0; nt < 16; nt++) {
        const int col = nt*8 + 2*t;
        *(uint32_t*)(ao + base0 + col) =
            pack2(__float2half_rn(o[nt][0] * inv0), __float2half_rn(o[nt][1] * inv0));
        *(uint32_t*)(ao + base1 + col) =
            pack2(__float2half_rn(o[nt][2] * inv1), __float2half_rn(o[nt][3] * inv1));
    }
}

// ---------------------------------------------------------------------------
// Launch: fork-join streams for concurrency inside the captured graph.
// ---------------------------------------------------------------------------
extern "C" void kernel_launch(void* const* d_in, const int* in_sizes, int n_in,
                              void* d_out, int out_size) {
    const float* x    = (const float*)d_in[0];
    const int*   mask = (const int*)  d_in[1];
    const float* Wq   = (const float*)d_in[2];
    const float* Wk   = (const float*)d_in[3];
    const float* Wv   = (const float*)d_in[4];
    const float* Wo   = (const float*)d_in[5];
    const float* qg   = (const float*)d_in[6];
    const float* kg   = (const float*)d_in[7];
    float* out = (float*)d_out;

    h16 *x16, *wq16, *wkv, *wo16, *q16, *kvp, *vtp, *aop;
    cudaGetSymbolAddress((void**)&x16,  g_x16);
    cudaGetSymbolAddress((void**)&wq16, g_wq16);
    cudaGetSymbolAddress((void**)&wkv,  g_wkv);
    cudaGetSymbolAddress((void**)&wo16, g_wo16);
    cudaGetSymbolAddress((void**)&q16,  g_q16);
    cudaGetSymbolAddress((void**)&kvp,  g_kv);
    cudaGetSymbolAddress((void**)&vtp,  g_vt);
    cudaGetSymbolAddress((void**)&aop,  g_ao);

    cudaFuncSetAttribute(k_flash, cudaFuncAttributeMaxDynamicSharedMemorySize,
                         FA_SMEM_BYTES);

    static cudaStream_t s1 = nullptr, s2 = nullptr;
    static cudaEvent_t e0 = nullptr, e1 = nullptr, e2 = nullptr, e3 = nullptr;
    if (!s1) {
        cudaStreamCreateWithFlags(&s1, cudaStreamNonBlocking);
        cudaStreamCreateWithFlags(&s2, cudaStreamNonBlocking);
        cudaEventCreateWithFlags(&e0, cudaEventDisableTiming);
        cudaEventCreateWithFlags(&e1, cudaEventDisableTiming);
        cudaEventCreateWithFlags(&e2, cudaEventDisableTiming);
        cudaEventCreateWithFlags(&e3, cudaEventDisableTiming);
    }

    const int M = B_ * L_;
    dim3 blk(256);

    // fork point (origin)
    cudaEventRecord(e0, 0);

    // s2: Wo conversion (independent of everything until O-proj)
    cudaStreamWaitEvent(s2, e0, 0);
    k_cvt_wo<<<1048576u/256u, 256, 0, s2>>>((const float4*)Wo);
    cudaEventRecord(e2, s2);

    // default: x + Wq + Wk|Wv conversion
    k_cvt_main<<<CS3/256u, 256>>>((const float4*)x, (const float4*)Wq,
                                  (const float4*)Wk, (const float4*)Wv);
    cudaEventRecord(e1, 0);

    // s1: KV projection (K half gets fused rms+rope) then V transpose
    cudaStreamWaitEvent(s1, e1, 0);
    k_gemm<2><<<dim3(KVD_/BN, M/BM), blk, SMEM_TB_BYTES, s1>>>(
        x16, D_, wkv, D_, kvp, KVD_, D_, kg);
    k_vtrans<<<dim3(L_/32, HD_/32, B_*KVH_), 256, 0, s1>>>(kvp, vtp);
    cudaEventRecord(e3, s1);

    // default: Q projection with fused rms+rope
    k_gemm<1><<<dim3(D_/BN, M/BM), blk, SMEM_TB_BYTES>>>(
        x16, D_, wq16, D_, q16, D_, D_, qg);

    // join s1, run flash
    cudaStreamWaitEvent(0, e3, 0);
    k_flash<<<dim3(L_/128, H_, B_), 256, FA_SMEM_BYTES>>>(q16, kvp, vtp, mask, aop);

    // join s2, output projection (fp32 out)
    cudaStreamWaitEvent(0, e2, 0);
    k_gemm<0><<<dim3(D_/BN, M/BM), blk, SMEM_TB_BYTES>>>(
        aop, D_, wo16, D_, out, D_, D_, nullptr);
}

// round 11
// speedup vs baseline: 1.9355x; 1.0508x over previous
#include <cuda_runtime.h>
#include <cuda_fp16.h>
#include <math.h>
#include <math_constants.h>
#include <stdint.h>

#define B_    2
#define L_    2048
#define D_    2048
#define H_    16
#define KVH_  4
#define HD_   128
#define KVD_  1024
#define EPS_  1e-6f

typedef __half h16;

// ---------------------------------------------------------------------------
// Static scratch (all fp16)
// ---------------------------------------------------------------------------
__device__ h16 g_x16 [B_*L_*D_];
__device__ h16 g_wq16[D_*D_];
__device__ h16 g_wkv [KVD_*D_];         // rows 0-511 = Wk, 512-1023 = Wv
__device__ h16 g_wo16[D_*D_];
__device__ h16 g_q16 [B_*L_*D_];
__device__ h16 g_kv  [B_*L_*KVD_];
__device__ h16 g_vt  [B_*KVH_*HD_*L_];
__device__ h16 g_ao  [B_*L_*D_];

// ---------------------------------------------------------------------------
// PTX helpers
// ---------------------------------------------------------------------------
__device__ __forceinline__ void mma_f16(float* c, const uint32_t* a, const uint32_t* b) {
    asm volatile(
        "mma.sync.aligned.m16n8k16.row.col.f32.f16.f16.f32 "
        "{%0,%1,%2,%3}, {%4,%5,%6,%7}, {%8,%9}, {%0,%1,%2,%3};\n"
        : "+f"(c[0]), "+f"(c[1]), "+f"(c[2]), "+f"(c[3])
        : "r"(a[0]), "r"(a[1]), "r"(a[2]), "r"(a[3]), "r"(b[0]), "r"(b[1]));
}

__device__ __forceinline__ void cp16(const h16* dst_s, const h16* src_g) {
    uint32_t d = (uint32_t)__cvta_generic_to_shared(dst_s);
    asm volatile("cp.async.cg.shared.global [%0], [%1], 16;\n"
                 :: "r"(d), "l"(src_g) : "memory");
}
__device__ __forceinline__ void cp_commit() {
    asm volatile("cp.async.commit_group;\n" ::: "memory");
}
template<int N>
__device__ __forceinline__ void cp_wait() {
    asm volatile("cp.async.wait_group %0;\n" :: "n"(N) : "memory");
}

// pack two fp32 -> fp16x2 in one instruction (lo = first arg, hi = second)
__device__ __forceinline__ uint32_t cvt2(float lo, float hi) {
    uint32_t r;
    asm("cvt.rn.f16x2.f32 %0, %1, %2;" : "=r"(r) : "f"(hi), "f"(lo));
    return r;
}

// ---------------------------------------------------------------------------
// GEMM: C[M,N] = A[M,K](h16) * B[N,K]^T(h16), fp32 acc.
// MODE 0: fp32 out. MODE 1: fp16 out + rmsnorm+rope (Q proj).
// MODE 2: fp16 out; rmsnorm+rope only for n0<512 (K half of KV proj).
// ---------------------------------------------------------------------------
#define BM 128
#define BN 128
#define BK 32
#define APAD 40

#define SM_A_HALVES (2*BM*APAD)
#define SM_B_HALVES (2*BN*APAD)
#define SMEM_TB_BYTES ((SM_A_HALVES + SM_B_HALVES)*2)   // 40960

#define INVF_C 0.2076205059304601f    // log2(10000)/64

template<int MODE>
__global__ __launch_bounds__(256, 2)
void k_gemm(const h16* __restrict__ A, int lda,
            const h16* __restrict__ Bh, int ldb,
            void* __restrict__ Cv, int ldc, int K,
            const float* __restrict__ gamma)
{
    extern __shared__ h16 sh[];
    h16* sA = sh;
    h16* sB = sh + SM_A_HALVES;

    const int tid = threadIdx.x;
    const int m0 = blockIdx.y * BM;
    const int n0 = blockIdx.x * BN;

    const h16* Ap = A  + (size_t)m0 * lda;
    const h16* Bp = Bh + (size_t)n0 * ldb;

    const int lane = tid & 31;
    const int g    = lane >> 2;
    const int t    = lane & 3;
    const int warp = tid >> 5;
    const int wm   = warp >> 2;
    const int wn   = warp & 3;

    float acc[4][4][4];
#pragma unroll
    for (int i = 0; i < 4; i++)
#pragma unroll
        for (int j = 0; j < 4; j++)
#pragma unroll
            for (int c = 0; c < 4; c++) acc[i][j][c] = 0.f;

    auto load_stage = [&](int s, int k0) {
#pragma unroll
        for (int i = 0; i < 2; i++) {
            int c   = tid + i * 256;
            int row = c >> 2, kc = c & 3;
            cp16(sA + (size_t)s*BM*APAD + row*APAD + kc*8,
                 Ap + (size_t)row * lda + k0 + kc*8);
        }
#pragma unroll
        for (int i = 0; i < 2; i++) {
            int c   = tid + i * 256;
            int row = c >> 2, kc = c & 3;
            cp16(sB + (size_t)s*BN*APAD + row*APAD + kc*8,
                 Bp + (size_t)row * ldb + k0 + kc*8);
        }
    };

    const int nk = K / BK;
    load_stage(0, 0);
    cp_commit();

    for (int ks = 0; ks < nk; ks++) {
        const int buf = ks & 1;
        if (ks + 1 < nk) {
            load_stage(buf ^ 1, (ks + 1) * BK);
            cp_commit();
            cp_wait<1>();
        } else {
            cp_wait<0>();
        }
        __syncthreads();

        const h16* sAb = sA + (size_t)buf*BM*APAD;
        const h16* sBb = sB + (size_t)buf*BN*APAD;

#pragma unroll
        for (int kk = 0; kk < 2; kk++) {
            const int ko = kk * 16;

            uint32_t ah[4][4];
#pragma unroll
            for (int mt = 0; mt < 4; mt++) {
                const int r = wm*64 + mt*16 + g;
                const h16* p0 = sAb + r*APAD + ko + 2*t;
                ah[mt][0] = *(const uint32_t*)(p0);
                ah[mt][1] = *(const uint32_t*)(p0 + 8*APAD);
                ah[mt][2] = *(const uint32_t*)(p0 + 8);
                ah[mt][3] = *(const uint32_t*)(p0 + 8*APAD + 8);
            }

            uint32_t bh[4][2];
#pragma unroll
            for (int nt = 0; nt < 4; nt++) {
                const int n = wn*32 + nt*8 + g;
                const h16* p0 = sBb + n*APAD + ko + 2*t;
                bh[nt][0] = *(const uint32_t*)(p0);
                bh[nt][1] = *(const uint32_t*)(p0 + 8);
            }

#pragma unroll
            for (int mt = 0; mt < 4; mt++)
#pragma unroll
                for (int nt = 0; nt < 4; nt++)
                    mma_f16(acc[mt][nt], ah[mt], bh[nt]);
        }
        __syncthreads();
    }

    // ---------------- epilogue ----------------
    if constexpr (MODE == 0) {
        float* C = (float*)Cv;
#pragma unroll
        for (int mt = 0; mt < 4; mt++) {
            const int r = m0 + wm*64 + mt*16 + g;
#pragma unroll
            for (int nt = 0; nt < 4; nt++) {
                const int c = n0 + wn*32 + nt*8 + 2*t;
                *reinterpret_cast<float2*>(&C[(size_t)r     * ldc + c]) =
                    make_float2(acc[mt][nt][0], acc[mt][nt][1]);
                *reinterpret_cast<float2*>(&C[(size_t)(r+8) * ldc + c]) =
                    make_float2(acc[mt][nt][2], acc[mt][nt][3]);
            }
        }
    } else {
        h16* C = (h16*)Cv;
        const bool dorms = (MODE == 1) || (n0 < 512);
        if (!dorms) {
#pragma unroll
            for (int mt = 0; mt < 4; mt++) {
                const int r = m0 + wm*64 + mt*16 + g;
#pragma unroll
                for (int nt = 0; nt < 4; nt++) {
                    const int c = n0 + wn*32 + nt*8 + 2*t;
                    *(uint32_t*)(&C[(size_t)r     * ldc + c]) =
                        cvt2(acc[mt][nt][0], acc[mt][nt][1]);
                    *(uint32_t*)(&C[(size_t)(r+8) * ldc + c]) =
                        cvt2(acc[mt][nt][2], acc[mt][nt][3]);
                }
            }
        } else {
            // fused rmsnorm + rope: block covers exactly one head (128 dims)
            float* red = (float*)sh;
            float part[4][2];
#pragma unroll
            for (int mt = 0; mt < 4; mt++)
#pragma unroll
                for (int hh = 0; hh < 2; hh++) {
                    float p = 0.f;
#pragma unroll
                    for (int nt = 0; nt < 4; nt++) {
                        float a0 = acc[mt][nt][2*hh], a1 = acc[mt][nt][2*hh+1];
                        p += a0*a0 + a1*a1;
                    }
                    p += __shfl_xor_sync(0xffffffffu, p, 1);
                    p += __shfl_xor_sync(0xffffffffu, p, 2);
                    part[mt][hh] = p;
                }
            if (t == 0) {
#pragma unroll
                for (int mt = 0; mt < 4; mt++)
#pragma unroll
                    for (int hh = 0; hh < 2; hh++)
                        red[(wm*64 + mt*16 + g + hh*8)*4 + wn] = part[mt][hh];
            }
            __syncthreads();

            float invv[4][2];
#pragma unroll
            for (int mt = 0; mt < 4; mt++)
#pragma unroll
                for (int hh = 0; hh < 2; hh++) {
                    int rl = wm*64 + mt*16 + g + hh*8;
                    float s = red[rl*4] + red[rl*4+1] + red[rl*4+2] + red[rl*4+3];
                    invv[mt][hh] = rsqrtf(s * (1.0f/HD_) + EPS_);
                }

            float invf[4], g0[4], g1[4];
#pragma unroll
            for (int nt = 0; nt < 4; nt++) {
                int p = wn*16 + nt*4 + t;
                invf[nt] = exp2f(-(float)p * INVF_C);
                g0[nt] = gamma[2*p];
                g1[nt] = gamma[2*p+1];
            }

#pragma unroll
            for (int mt = 0; mt < 4; mt++)
#pragma unroll
                for (int hh = 0; hh < 2; hh++) {
                    const int r  = m0 + wm*64 + mt*16 + g + hh*8;
                    const float fl = (float)(r & (L_-1));
                    const float iv = invv[mt][hh];
#pragma unroll
                    for (int nt = 0; nt < 4; nt++) {
                        float sn, cs;
                        sincosf(fl * invf[nt], &sn, &cs);
                        float re = acc[mt][nt][2*hh]   * iv * g0[nt];
                        float im = acc[mt][nt][2*hh+1] * iv * g1[nt];
                        h16* dst = C + (size_t)r * ldc + n0 + wn*32 + nt*8 + 2*t;
                        *(uint32_t*)dst = cvt2(re*cs - im*sn, re*sn + im*cs);
                    }
                }
        }
    }
}

// ---------------------------------------------------------------------------
// fp32->fp16 conversion
// ---------------------------------------------------------------------------
#define CS0 2097152u
#define CS1 (CS0 + 1048576u)
#define CS2 (CS1 + 262144u)
#define CS3 (CS2 + 262144u)

__device__ __forceinline__ ushort4 cvt4(float4 v) {
    uint32_t lo = 0, hi = 0;
    asm("cvt.rn.f16x2.f32 %0, %1, %2;" : "=r"(lo) : "f"(v.y), "f"(v.x));
    asm("cvt.rn.f16x2.f32 %0, %1, %2;" : "=r"(hi) : "f"(v.w), "f"(v.z));
    ushort4 r;
    r.x = (unsigned short)(lo & 0xffff);
    r.y = (unsigned short)(lo >> 16);
    r.z = (unsigned short)(hi & 0xffff);
    r.w = (unsigned short)(hi >> 16);
    return r;
}

__global__ void k_cvt_main(const float4* __restrict__ x, const float4* __restrict__ wq,
                           const float4* __restrict__ wk, const float4* __restrict__ wv)
{
    uint32_t i = blockIdx.x * 256u + threadIdx.x;
    ushort4* xh  = (ushort4*)g_x16;
    ushort4* qh  = (ushort4*)g_wq16;
    ushort4* kvh = (ushort4*)g_wkv;
    if (i < CS0)      xh [i]                  = cvt4(x [i]);
    else if (i < CS1) qh [i - CS0]            = cvt4(wq[i - CS0]);
    else if (i < CS2) kvh[i - CS1]            = cvt4(wk[i - CS1]);
    else if (i < CS3) kvh[i - CS2 + 262144u]  = cvt4(wv[i - CS2]);
}

__global__ void k_cvt_wo(const float4* __restrict__ wo)
{
    uint32_t i = blockIdx.x * 256u + threadIdx.x;
    ((ushort4*)g_wo16)[i] = cvt4(wo[i]);
}

// ---------------------------------------------------------------------------
// V transpose: kv fp16 [b][l][1024] (v at +512) -> vt [b][kvh][d][L]
// ---------------------------------------------------------------------------
__global__ void k_vtrans(const h16* __restrict__ KV, h16* __restrict__ Vt)
{
    __shared__ h16 tile[32][34];
    const int tx = threadIdx.x & 31;
    const int ty = threadIdx.x >> 5;
    const int l0 = blockIdx.x * 32;
    const int d0 = blockIdx.y * 32;
    const int z  = blockIdx.z;
    const int b  = z >> 2, kvh = z & 3;

#pragma unroll
    for (int i = 0; i < 4; i++) {
        int l = l0 + ty + i*8;
        tile[ty + i*8][tx] =
            KV[(size_t)(b*L_ + l) * KVD_ + 512 + kvh * HD_ + d0 + tx];
    }
    __syncthreads();
#pragma unroll
    for (int i = 0; i < 4; i++) {
        int d = d0 + ty + i*8;
        size_t idx = ((size_t)(b*KVH_ + kvh) * HD_ + d) * L_ + l0 + tx;
        Vt[idx] = tile[tx][ty + i*8];
    }
}

// ---------------------------------------------------------------------------
// Fused flash attention, fixed-shift softmax, tiles order-independent.
// 128 threads (4 warps), q-tile 64, occupancy 2 -> cross-CTA softmax/MMA overlap.
// ---------------------------------------------------------------------------
#define QPAD 136
#define VPAD 72

#define QPL  (64*QPAD)            // 8704
#define KPL  (64*QPAD)            // 8704
#define VPL  (128*VPAD)           // 9216
#define QS_OFF 0
#define KS_OFF QPL
#define VS_OFF (KS_OFF + 2*KPL)
#define MS_OFF_H (VS_OFF + 2*VPL)
#define FA_SMEM_BYTES (MS_OFF_H*2 + 2*64*4)   // 89600

__global__ __launch_bounds__(128, 2)
void k_flash(const h16* __restrict__ qh,
             const h16* __restrict__ kv,
             const h16* __restrict__ vt,
             const int* __restrict__ mask,
             h16* __restrict__ ao)
{
    extern __shared__ h16 sm[];
    h16*   Qs = sm + QS_OFF;
    h16*   Ks = sm + KS_OFF;
    h16*   Vs = sm + VS_OFF;
    float* Ms = (float*)(sm + MS_OFF_H);

    const int tid  = threadIdx.x;
    const int lane = tid & 31;
    const int g    = lane >> 2;
    const int t    = lane & 3;
    const int w    = tid >> 5;          // 0..3

    const int qt = blockIdx.x, h = blockIdx.y, b = blockIdx.z;
    const int kvh = h >> 2;
    const int q0  = qt * 64;

    const h16* Qg = qh + ((size_t)(b*L_ + q0)) * D_ + h * HD_;
    const h16* Kg = kv + ((size_t)(b*L_)) * KVD_ + kvh * HD_;
    const h16* Vg = vt + ((size_t)(b*KVH_ + kvh)) * HD_ * L_;

    // Q load (once): 64 rows x 16 chunks = 1024 cp16 over 128 threads
#pragma unroll
    for (int i = 0; i < 8; i++) {
        int c = tid + i * 128;
        int row = c >> 4, ch = c & 15;
        cp16(Qs + row*QPAD + ch*8, Qg + (size_t)row * D_ + ch*8);
    }

    auto load_stage = [&](int s, int kt) {
        const int j0 = kt * 64;
#pragma unroll
        for (int i = 0; i < 8; i++) {          // K: 64 rows x 16 chunks
            int c = tid + i * 128;
            int row = c >> 4, ch = c & 15;
            cp16(Ks + s*KPL + row*QPAD + ch*8,
                 Kg + (size_t)(j0 + row) * KVD_ + ch*8);
        }
#pragma unroll
        for (int i = 0; i < 8; i++) {          // V: 128 rows x 8 chunks
            int c = tid + i * 128;
            int row = c >> 3, ch = c & 7;
            cp16(Vs + s*VPL + row*VPAD + ch*8,
                 Vg + (size_t)row * L_ + j0 + ch*8);
        }
        if (tid < 64)
            Ms[s*64 + tid] = mask[b*L_ + j0 + tid] ? -6.0f : -1e30f;
    };

    load_stage(0, 0);
    cp_commit();

    float o[16][4];
#pragma unroll
    for (int i = 0; i < 16; i++)
#pragma unroll
        for (int c = 0; c < 4; c++) o[i][c] = 0.f;

    float lsum0 = 0.f, lsum1 = 0.f;
    const float sc = 0.08838834764831845f;

    const int NT_ = L_ / 64;
    for (int kt = 0; kt < NT_; kt++) {
        const int buf = kt & 1;
        if (kt + 1 < NT_) {
            load_stage(buf ^ 1, kt + 1);
            cp_commit();
            cp_wait<1>();
        } else {
            cp_wait<0>();
        }
        __syncthreads();

        // ---- S = Q K^T : per warp m16 x n64 x k128 ----
        float s[8][4];
#pragma unroll
        for (int nt = 0; nt < 8; nt++)
#pragma unroll
            for (int c = 0; c < 4; c++) s[nt][c] = 0.f;

        const h16* qb = Qs + (w*16 + g)*QPAD + 2*t;
        const h16* kb = Ks + buf*KPL + g*QPAD + 2*t;

#pragma unroll
        for (int kk = 0; kk < 8; kk++) {
            const int ko = kk * 16;
            uint32_t ah[4];
            ah[0] = *(const uint32_t*)(qb + ko);
            ah[1] = *(const uint32_t*)(qb + ko + 8*QPAD);
            ah[2] = *(const uint32_t*)(qb + ko + 8);
            ah[3] = *(const uint32_t*)(qb + ko + 8*QPAD + 8);
#pragma unroll
            for (int nt = 0; nt < 8; nt++) {
                uint32_t bh[2];
                const h16* pk = kb + nt*8*QPAD + ko;
                bh[0] = *(const uint32_t*)(pk);
                bh[1] = *(const uint32_t*)(pk + 8);
                mma_f16(s[nt], ah, bh);
            }
        }

        // ---- fixed-shift exp + sum + fp16 P fragments ----
        const float* msf = Ms + buf*64;
        uint32_t pah[4][4];
#pragma unroll
        for (int kk = 0; kk < 4; kk++) {
            const int n0t = 2*kk, n1t = 2*kk + 1;
            float b00 = msf[8*n0t + 2*t], b01 = msf[8*n0t + 2*t + 1];
            float b10 = msf[8*n1t + 2*t], b11 = msf[8*n1t + 2*t + 1];
            float p00 = __expf(s[n0t][0]*sc + b00);
            float p01 = __expf(s[n0t][1]*sc + b01);
            float p02 = __expf(s[n0t][2]*sc + b00);
            float p03 = __expf(s[n0t][3]*sc + b01);
            float p10 = __expf(s[n1t][0]*sc + b10);
            float p11 = __expf(s[n1t][1]*sc + b11);
            float p12 = __expf(s[n1t][2]*sc + b10);
            float p13 = __expf(s[n1t][3]*sc + b11);
            lsum0 += p00 + p01 + p10 + p11;
            lsum1 += p02 + p03 + p12 + p13;
            pah[kk][0] = cvt2(p00, p01);
            pah[kk][1] = cvt2(p02, p03);
            pah[kk][2] = cvt2(p10, p11);
            pah[kk][3] = cvt2(p12, p13);
        }

        // ---- O += P V : per warp m16 x n128 x k64 ----
        const h16* vb = Vs + buf*VPL + g*VPAD + 2*t;
#pragma unroll
        for (int kk = 0; kk < 4; kk++) {
            const int ko = kk * 16;
#pragma unroll
            for (int nt = 0; nt < 16; nt++) {
                uint32_t bh[2];
                const h16* pv = vb + nt*8*VPAD + ko;
                bh[0] = *(const uint32_t*)(pv);
                bh[1] = *(const uint32_t*)(pv + 8);
                mma_f16(o[nt], pah[kk], bh);
            }
        }
        __syncthreads();
    }

    lsum0 += __shfl_xor_sync(0xffffffffu, lsum0, 1);
    lsum0 += __shfl_xor_sync(0xffffffffu, lsum0, 2);
    lsum1 += __shfl_xor_sync(0xffffffffu, lsum1, 1);
    lsum1 += __shfl_xor_sync(0xffffffffu, lsum1, 2);

    const float inv0 = lsum0 > 0.f ? 1.f / lsum0 : 0.f;
    const float inv1 = lsum1 > 0.f ? 1.f / lsum1 : 0.f;
    const int row0 = q0 + w*16 + g;
    const size_t base0 = (size_t)(b*L_ + row0) * D_ + h * HD_;
    const size_t base1 = base0 + 8 * (size_t)D_;

#pragma unroll
    for (int nt = 0; nt < 16; nt++) {
        const int col = nt*8 + 2*t;
        *(uint32_t*)(ao + base0 + col) = cvt2(o[nt][0] * inv0, o[nt][1] * inv0);
        *(uint32_t*)(ao + base1 + col) = cvt2(o[nt][2] * inv1, o[nt][3] * inv1);
    }
}

// ---------------------------------------------------------------------------
// Launch: fork-join streams for concurrency inside the captured graph.
// ---------------------------------------------------------------------------
extern "C" void kernel_launch(void* const* d_in, const int* in_sizes, int n_in,
                              void* d_out, int out_size) {
    const float* x    = (const float*)d_in[0];
    const int*   mask = (const int*)  d_in[1];
    const float* Wq   = (const float*)d_in[2];
    const float* Wk   = (const float*)d_in[3];
    const float* Wv   = (const float*)d_in[4];
    const float* Wo   = (const float*)d_in[5];
    const float* qg   = (const float*)d_in[6];
    const float* kg   = (const float*)d_in[7];
    float* out = (float*)d_out;

    h16 *x16, *wq16, *wkv, *wo16, *q16, *kvp, *vtp, *aop;
    cudaGetSymbolAddress((void**)&x16,  g_x16);
    cudaGetSymbolAddress((void**)&wq16, g_wq16);
    cudaGetSymbolAddress((void**)&wkv,  g_wkv);
    cudaGetSymbolAddress((void**)&wo16, g_wo16);
    cudaGetSymbolAddress((void**)&q16,  g_q16);
    cudaGetSymbolAddress((void**)&kvp,  g_kv);
    cudaGetSymbolAddress((void**)&vtp,  g_vt);
    cudaGetSymbolAddress((void**)&aop,  g_ao);

    cudaFuncSetAttribute(k_flash, cudaFuncAttributeMaxDynamicSharedMemorySize,
                         FA_SMEM_BYTES);

    static cudaStream_t s1 = nullptr, s2 = nullptr;
    static cudaEvent_t e0 = nullptr, e1 = nullptr, e2 = nullptr, e3 = nullptr;
    if (!s1) {
        cudaStreamCreateWithFlags(&s1, cudaStreamNonBlocking);
        cudaStreamCreateWithFlags(&s2, cudaStreamNonBlocking);
        cudaEventCreateWithFlags(&e0, cudaEventDisableTiming);
        cudaEventCreateWithFlags(&e1, cudaEventDisableTiming);
        cudaEventCreateWithFlags(&e2, cudaEventDisableTiming);
        cudaEventCreateWithFlags(&e3, cudaEventDisableTiming);
    }

    const int M = B_ * L_;
    dim3 blk(256);

    // fork point
    cudaEventRecord(e0, 0);

    // s2: Wo conversion (independent until O-proj)
    cudaStreamWaitEvent(s2, e0, 0);
    k_cvt_wo<<<1048576u/256u, 256, 0, s2>>>((const float4*)Wo);
    cudaEventRecord(e2, s2);

    // default: x + Wq + Wk|Wv conversion
    k_cvt_main<<<CS3/256u, 256>>>((const float4*)x, (const float4*)Wq,
                                  (const float4*)Wk, (const float4*)Wv);
    cudaEventRecord(e1, 0);

    // s1: KV projection (K half fused rms+rope) then V transpose
    cudaStreamWaitEvent(s1, e1, 0);
    k_gemm<2><<<dim3(KVD_/BN, M/BM), blk, SMEM_TB_BYTES, s1>>>(
        x16, D_, wkv, D_, kvp, KVD_, D_, kg);
    k_vtrans<<<dim3(L_/32, HD_/32, B_*KVH_), 256, 0, s1>>>(kvp, vtp);
    cudaEventRecord(e3, s1);

    // default: Q projection with fused rms+rope
    k_gemm<1><<<dim3(D_/BN, M/BM), blk, SMEM_TB_BYTES>>>(
        x16, D_, wq16, D_, q16, D_, D_, qg);

    // join s1, run flash (q-tile 64, 128 threads, occ 2)
    cudaStreamWaitEvent(0, e3, 0);
    k_flash<<<dim3(L_/64, H_, B_), 128, FA_SMEM_BYTES>>>(q16, kvp, vtp, mask, aop);

    // join s2, output projection (fp32 out)
    cudaStreamWaitEvent(0, e2, 0);
    k_gemm<0><<<dim3(D_/BN, M/BM), blk, SMEM_TB_BYTES>>>(
        aop, D_, wo16, D_, out, D_, D_, nullptr);
}